// round 5
// baseline (speedup 1.0000x reference)
#include <cuda_runtime.h>
#include <math.h>
#include <stdint.h>

// Problem constants
#define DD    512
#define KC    1024
#define QL    8
#define NTOK  16384
#define MT    64          // tokens per CTA
#define CCH   128         // codes per chunk
#define DS    32          // d-slice per smem stage
#define NCTA  (NTOK / MT) // 256

// Paired (d/2-interleaved) smem strides, in floats
#define RP    132         // res: [256 dp][64 tok * 2] + pad (mult of 4 for 16B LDS)
#define PSTR  264         // cbs: [16 dp][128 code * 2] + pad (mult of 4)

#define IDXOFF ((size_t)NTOK * DD)           // 8388608
#define SCLOFF (IDXOFF + (size_t)NTOK * QL)  // 8519680

// packed f32x2 FMA: d.lo = fma(a.lo,b.lo,d.lo); d.hi likewise (sm_100+)
#define FMA2(acc, a, b) \
    asm("fma.rn.f32x2 %0, %1, %2, %0;" : "+l"(acc) : "l"(a), "l"(b))

// Scratch (static device arrays; no cudaMalloc anywhere)
__device__ float  g_csq[QL * KC];
__device__ int    g_cnt[QL * KC];
__device__ double g_commit[QL];
__device__ float  g_qsum[(size_t)NTOK * DD];

// ---------------------------------------------------------------------------
__global__ void rvq_prep(const float* __restrict__ cb) {
    int i = blockIdx.x * blockDim.x + threadIdx.x;
    if (i < QL * KC) {
        const float* c = cb + (size_t)i * DD;
        float s = 0.f;
        for (int d = 0; d < DD; ++d) { float v = c[d]; s += v * v; }
        g_csq[i] = s;
        g_cnt[i] = 0;
    }
    if (i < QL) g_commit[i] = 0.0;
}

// ---------------------------------------------------------------------------
// Fused main kernel: residual tile resident in smem (d-pair interleaved)
// across all 8 levels. Distance GEMM uses packed fma.rn.f32x2 (2 MACs/issue).
// ---------------------------------------------------------------------------
__global__ void __launch_bounds__(256, 1)
rvq_main(const float* __restrict__ x, const float* __restrict__ cb,
         float* __restrict__ out) {
    extern __shared__ char smraw[];
    float* res  = (float*)smraw;                    // [256 dp][RP]
    float* cbs  = res + (DD / 2) * RP;              // [16 dp][PSTR]
    float* redv = cbs + (DS / 2) * PSTR;            // [16][64]
    int*   redi = (int*)(redv + 16 * 64);           // [16][64]
    float* rsqp = (float*)(redi + 16 * 64);         // [4][64]
    float* rsq  = rsqp + 4 * 64;                    // [64]
    int*   idxs = (int*)(rsq + 64);                 // [64]

    const int tid  = threadIdx.x;
    const int tok0 = blockIdx.x * MT;

    // GEMM mapping: 16 token-groups x 16 code-groups
    const int tg = tid & 15;   // tokens tg*4 .. tg*4+3
    const int cg = tid >> 4;   // codes  cg*8 .. cg*8+7 within chunk

    // update-phase mapping: 4 threads per token
    const int tsub  = tid & 3;
    const int tloc  = tid >> 2;         // 0..63
    const int dbase = tsub * 128;

    // ---- initial load: x -> res (d-pair interleaved) + rsq partials
    {
        const float* xp = x + (size_t)(tok0 + tloc) * DD + dbase;
        float s = 0.f;
        #pragma unroll 4
        for (int j = 0; j < 128; j += 4) {
            float4 v = *(const float4*)(xp + j);
            int dp = (dbase + j) >> 1;
            *(float2*)&res[dp * RP + tloc * 2]       = make_float2(v.x, v.y);
            *(float2*)&res[(dp + 1) * RP + tloc * 2] = make_float2(v.z, v.w);
            s += v.x * v.x; s += v.y * v.y; s += v.z * v.z; s += v.w * v.w;
        }
        rsqp[tsub * 64 + tloc] = s;
    }
    __syncthreads();
    if (tid < MT)
        rsq[tid] = ((rsqp[tid] + rsqp[64 + tid]) + rsqp[128 + tid]) + rsqp[192 + tid];

    for (int l = 0; l < QL; ++l) {
        const float* cbl  = cb + (size_t)l * KC * DD;
        const float* csql = g_csq + l * KC;

        float bestv[4]; int besti[4];
        #pragma unroll
        for (int i = 0; i < 4; ++i) { bestv[i] = __int_as_float(0x7f800000); besti[i] = 0; }

        unsigned long long acc[4][8];
        float4 pf[4];
        {   // prefetch slice 0 of chunk 0
            #pragma unroll
            for (int i = 0; i < 4; ++i) {
                int f4 = i * 256 + tid;
                int code = f4 >> 3, seg = f4 & 7;
                pf[i] = *(const float4*)(cbl + (size_t)code * DD + (seg << 2));
            }
        }

        #pragma unroll 1
        for (int step = 0; step < (KC / CCH) * (DD / DS); ++step) {
            const int kc = (step >> 4) * CCH;
            const int sl = step & 15;

            if (sl == 0) {
                #pragma unroll
                for (int i = 0; i < 4; ++i)
                    #pragma unroll
                    for (int j = 0; j < 8; ++j) acc[i][j] = 0ULL;
            }

            __syncthreads();   // previous compute done before overwriting cbs
            #pragma unroll
            for (int i = 0; i < 4; ++i) {
                int f4 = i * 256 + tid;
                int code = f4 >> 3, seg = f4 & 7;
                int dpl = seg << 1;   // 4 dims -> local dp, dp+1
                *(float2*)&cbs[dpl * PSTR + code * 2]       = make_float2(pf[i].x, pf[i].y);
                *(float2*)&cbs[(dpl + 1) * PSTR + code * 2] = make_float2(pf[i].z, pf[i].w);
            }
            __syncthreads();

            // prefetch next slice (global latency hidden under FMA loop)
            if (step + 1 < (KC / CCH) * (DD / DS)) {
                const int nkc = ((step + 1) >> 4) * CCH;
                const int nd0 = ((step + 1) & 15) * DS;
                #pragma unroll
                for (int i = 0; i < 4; ++i) {
                    int f4 = i * 256 + tid;
                    int code = f4 >> 3, seg = f4 & 7;
                    pf[i] = *(const float4*)(cbl + (size_t)(nkc + code) * DD + nd0 + (seg << 2));
                }
            }

            const int d0p = sl * (DS / 2);
            #pragma unroll 4
            for (int ddp = 0; ddp < DS / 2; ++ddp) {
                const float* ap = &res[(d0p + ddp) * RP + (tg << 3)];
                const float* bp = &cbs[ddp * PSTR + (cg << 4)];
                ulonglong2 A0 = *(const ulonglong2*)ap;        // tok pairs 0,1
                ulonglong2 A1 = *(const ulonglong2*)(ap + 4);  // tok pairs 2,3
                ulonglong2 B0 = *(const ulonglong2*)bp;        // code pairs 0,1
                ulonglong2 B1 = *(const ulonglong2*)(bp + 4);  // 2,3
                ulonglong2 B2 = *(const ulonglong2*)(bp + 8);  // 4,5
                ulonglong2 B3 = *(const ulonglong2*)(bp + 12); // 6,7
                unsigned long long pa[4] = {A0.x, A0.y, A1.x, A1.y};
                unsigned long long pb[8] = {B0.x, B0.y, B1.x, B1.y,
                                            B2.x, B2.y, B3.x, B3.y};
                #pragma unroll
                for (int i = 0; i < 4; ++i)
                    #pragma unroll
                    for (int j = 0; j < 8; ++j)
                        FMA2(acc[i][j], pa[i], pb[j]);
            }

            if (sl == 15) {
                // dot = even-dim sum + odd-dim sum; dist = fl(fl(rsq-2*dot)+csq)
                #pragma unroll
                for (int i = 0; i < 4; ++i) {
                    float rq = rsq[(tg << 2) + i];
                    #pragma unroll
                    for (int j = 0; j < 8; ++j) {
                        float lo = __uint_as_float((unsigned)acc[i][j]);
                        float hi = __uint_as_float((unsigned)(acc[i][j] >> 32));
                        float dot = lo + hi;
                        int code = kc + (cg << 3) + j;
                        float dist = fmaf(-2.f, dot, rq) + csql[code];
                        if (dist < bestv[i]) { bestv[i] = dist; besti[i] = code; }
                    }
                }
            }
        }

        // ---- cross-thread argmin reduce (lowest index wins ties)
        __syncthreads();
        #pragma unroll
        for (int i = 0; i < 4; ++i) {
            redv[cg * 64 + (tg << 2) + i] = bestv[i];
            redi[cg * 64 + (tg << 2) + i] = besti[i];
        }
        __syncthreads();
        if (tid < MT) {
            float bv = redv[tid]; int bi = redi[tid];
            #pragma unroll 1
            for (int c = 1; c < 16; ++c) {
                float v = redv[c * 64 + tid]; int ix = redi[c * 64 + tid];
                if (v < bv || (v == bv && ix < bi)) { bv = v; bi = ix; }
            }
            idxs[tid] = bi;
            out[IDXOFF + (size_t)(tok0 + tid) * QL + l] = (float)bi;
            atomicAdd(&g_cnt[l * KC + bi], 1);
        }
        __syncthreads();

        // ---- gather + residual/qsum update + rsq partials for next level
        {
            const int myidx = idxs[tloc];
            const float* qv = cbl + (size_t)myidx * DD + dbase;
            float* qs = g_qsum + (size_t)(tok0 + tloc) * DD + dbase;
            const float* xp = x + (size_t)(tok0 + tloc) * DD + dbase;
            float* op = out + (size_t)(tok0 + tloc) * DD + dbase;
            float s = 0.f;
            #pragma unroll 4
            for (int j = 0; j < 128; j += 4) {
                float4 q = *(const float4*)(qv + j);
                int dp = (dbase + j) >> 1;
                float2* p01 = (float2*)&res[dp * RP + tloc * 2];
                float2* p23 = (float2*)&res[(dp + 1) * RP + tloc * 2];
                float2 r01 = *p01, r23 = *p23;
                float r0 = r01.x - q.x, r1 = r01.y - q.y;
                float r2 = r23.x - q.z, r3 = r23.y - q.w;
                *p01 = make_float2(r0, r1);
                *p23 = make_float2(r2, r3);
                s += r0 * r0; s += r1 * r1; s += r2 * r2; s += r3 * r3;

                float4 qa;
                if (l == 0) {
                    qa = q;
                } else {
                    float4 o = *(const float4*)(qs + j);
                    qa.x = o.x + q.x; qa.y = o.y + q.y;
                    qa.z = o.z + q.z; qa.w = o.w + q.w;
                }
                *(float4*)(qs + j) = qa;

                if (l == QL - 1) {
                    float4 xv = *(const float4*)(xp + j);
                    float4 ov;
                    ov.x = xv.x + (qa.x - xv.x);
                    ov.y = xv.y + (qa.y - xv.y);
                    ov.z = xv.z + (qa.z - xv.z);
                    ov.w = xv.w + (qa.w - xv.w);
                    *(float4*)(op + j) = ov;
                }
            }
            rsqp[tsub * 64 + tloc] = s;
        }
        __syncthreads();
        if (tid < MT)
            rsq[tid] = ((rsqp[tid] + rsqp[64 + tid]) + rsqp[128 + tid]) + rsqp[192 + tid];
        __syncthreads();
        if (tid == 0) {
            double cs = 0.0;
            for (int t = 0; t < MT; ++t) cs += (double)rsq[t];
            atomicAdd(&g_commit[l], cs);
        }
    }
}

// ---------------------------------------------------------------------------
__global__ void rvq_fin(float* __restrict__ out) {
    __shared__ double red[256];
    const int tid = threadIdx.x;
    double psum = 0.0;
    for (int l = 0; l < QL; ++l) {
        double s = 0.0;
        for (int k = tid; k < KC; k += 256) {
            double p = (double)g_cnt[l * KC + k] / (double)NTOK;
            s += p * log(p + 1e-10);
        }
        red[tid] = s;
        __syncthreads();
        for (int off = 128; off > 0; off >>= 1) {
            if (tid < off) red[tid] += red[tid + off];
            __syncthreads();
        }
        if (tid == 0) psum += exp(-red[0]);
        __syncthreads();
    }
    if (tid == 0) {
        double closs = 0.0;
        for (int l = 0; l < QL; ++l)
            closs += g_commit[l] / ((double)NTOK * (double)DD);
        out[SCLOFF]     = (float)(0.25 * closs);
        out[SCLOFF + 1] = (float)(psum / (double)QL);
    }
}

// ---------------------------------------------------------------------------
extern "C" void kernel_launch(void* const* d_in, const int* in_sizes, int n_in,
                              void* d_out, int out_size) {
    const float* x  = (const float*)d_in[0];
    const float* cb = (const float*)d_in[1];
    float* out = (float*)d_out;

    const int smem = ((DD / 2) * RP + (DS / 2) * PSTR +
                      16 * 64 * 2 + 4 * 64 + 64 + 64) * 4;
    cudaFuncSetAttribute(rvq_main, cudaFuncAttributeMaxDynamicSharedMemorySize, smem);

    rvq_prep<<<(QL * KC + 255) / 256, 256>>>(cb);
    rvq_main<<<NCTA, 256, smem>>>(x, cb, out);
    rvq_fin<<<1, 256>>>(out);
}

// round 6
// speedup vs baseline: 1.0025x; 1.0025x over previous
#include <cuda_runtime.h>
#include <math.h>
#include <stdint.h>

// Problem constants
#define DD    512
#define KC    1024
#define QL    8
#define NTOK  16384
#define MT    64          // tokens per CTA
#define CCH   128         // codes per chunk
#define DS    32          // d-slice per smem stage
#define NCTA  (NTOK / MT) // 256

// Paired (d/2-interleaved) smem strides, in floats
#define RP    132         // res: [256 dp][64 tok * 2] + pad (mult of 4 for 16B LDS)
#define PSTR  264         // cbs: [16 dp][128 code * 2] + pad (mult of 4)

#define IDXOFF ((size_t)NTOK * DD)           // 8388608
#define SCLOFF (IDXOFF + (size_t)NTOK * QL)  // 8519680

// packed f32x2 FMA: d.lo = fma(a.lo,b.lo,d.lo); d.hi likewise (sm_100+)
#define FMA2(acc, a, b) \
    asm("fma.rn.f32x2 %0, %1, %2, %0;" : "+l"(acc) : "l"(a), "l"(b))

// Scratch (static device arrays; no cudaMalloc anywhere)
__device__ float  g_csq[QL * KC];
__device__ int    g_cnt[QL * KC];
__device__ double g_commit[QL];
__device__ float  g_qsum[(size_t)NTOK * DD];

// ---------------------------------------------------------------------------
__global__ void rvq_prep(const float* __restrict__ cb) {
    int i = blockIdx.x * blockDim.x + threadIdx.x;
    if (i < QL * KC) {
        const float* c = cb + (size_t)i * DD;
        float s = 0.f;
        for (int d = 0; d < DD; ++d) { float v = c[d]; s += v * v; }
        g_csq[i] = s;
        g_cnt[i] = 0;
    }
    if (i < QL) g_commit[i] = 0.0;
}

// ---------------------------------------------------------------------------
// Fused main kernel: residual tile resident in smem (d-pair interleaved)
// across all 8 levels. Distance GEMM uses packed fma.rn.f32x2 (2 MACs/issue).
// ---------------------------------------------------------------------------
__global__ void __launch_bounds__(256, 1)
rvq_main(const float* __restrict__ x, const float* __restrict__ cb,
         float* __restrict__ out) {
    extern __shared__ char smraw[];
    float* res  = (float*)smraw;                    // [256 dp][RP]
    float* cbs  = res + (DD / 2) * RP;              // [16 dp][PSTR]
    float* redv = cbs + (DS / 2) * PSTR;            // [16][64]
    int*   redi = (int*)(redv + 16 * 64);           // [16][64]
    float* rsqp = (float*)(redi + 16 * 64);         // [4][64]
    float* rsq  = rsqp + 4 * 64;                    // [64]
    int*   idxs = (int*)(rsq + 64);                 // [64]

    const int tid  = threadIdx.x;
    const int tok0 = blockIdx.x * MT;

    // GEMM mapping: 16 token-groups x 16 code-groups
    const int tg = tid & 15;   // tokens tg*4 .. tg*4+3
    const int cg = tid >> 4;   // codes  cg*8 .. cg*8+7 within chunk

    // update-phase mapping: 4 threads per token
    const int tsub  = tid & 3;
    const int tloc  = tid >> 2;         // 0..63
    const int dbase = tsub * 128;

    // ---- initial load: x -> res (d-pair interleaved) + rsq partials
    {
        const float* xp = x + (size_t)(tok0 + tloc) * DD + dbase;
        float s = 0.f;
        #pragma unroll 4
        for (int j = 0; j < 128; j += 4) {
            float4 v = *(const float4*)(xp + j);
            int dp = (dbase + j) >> 1;
            *(float2*)&res[dp * RP + tloc * 2]       = make_float2(v.x, v.y);
            *(float2*)&res[(dp + 1) * RP + tloc * 2] = make_float2(v.z, v.w);
            s += v.x * v.x; s += v.y * v.y; s += v.z * v.z; s += v.w * v.w;
        }
        rsqp[tsub * 64 + tloc] = s;
    }
    __syncthreads();
    if (tid < MT)
        rsq[tid] = ((rsqp[tid] + rsqp[64 + tid]) + rsqp[128 + tid]) + rsqp[192 + tid];

    for (int l = 0; l < QL; ++l) {
        const float* cbl  = cb + (size_t)l * KC * DD;
        const float* csql = g_csq + l * KC;

        float bestv[4]; int besti[4];
        #pragma unroll
        for (int i = 0; i < 4; ++i) { bestv[i] = __int_as_float(0x7f800000); besti[i] = 0; }

        unsigned long long acc[4][8];
        float4 pf[4];
        {   // prefetch slice 0 of chunk 0
            #pragma unroll
            for (int i = 0; i < 4; ++i) {
                int f4 = i * 256 + tid;
                int code = f4 >> 3, seg = f4 & 7;
                pf[i] = *(const float4*)(cbl + (size_t)code * DD + (seg << 2));
            }
        }

        #pragma unroll 1
        for (int step = 0; step < (KC / CCH) * (DD / DS); ++step) {
            const int kc = (step >> 4) * CCH;
            const int sl = step & 15;

            if (sl == 0) {
                #pragma unroll
                for (int i = 0; i < 4; ++i)
                    #pragma unroll
                    for (int j = 0; j < 8; ++j) acc[i][j] = 0ULL;
            }

            __syncthreads();   // previous compute done before overwriting cbs
            #pragma unroll
            for (int i = 0; i < 4; ++i) {
                int f4 = i * 256 + tid;
                int code = f4 >> 3, seg = f4 & 7;
                int dpl = seg << 1;   // 4 dims -> local dp, dp+1
                *(float2*)&cbs[dpl * PSTR + code * 2]       = make_float2(pf[i].x, pf[i].y);
                *(float2*)&cbs[(dpl + 1) * PSTR + code * 2] = make_float2(pf[i].z, pf[i].w);
            }
            __syncthreads();

            // prefetch next slice (global latency hidden under FMA loop)
            if (step + 1 < (KC / CCH) * (DD / DS)) {
                const int nkc = ((step + 1) >> 4) * CCH;
                const int nd0 = ((step + 1) & 15) * DS;
                #pragma unroll
                for (int i = 0; i < 4; ++i) {
                    int f4 = i * 256 + tid;
                    int code = f4 >> 3, seg = f4 & 7;
                    pf[i] = *(const float4*)(cbl + (size_t)(nkc + code) * DD + nd0 + (seg << 2));
                }
            }

            const int d0p = sl * (DS / 2);
            #pragma unroll 4
            for (int ddp = 0; ddp < DS / 2; ++ddp) {
                const float* ap = &res[(d0p + ddp) * RP + (tg << 3)];
                const float* bp = &cbs[ddp * PSTR + (cg << 4)];
                ulonglong2 A0 = *(const ulonglong2*)ap;        // tok pairs 0,1
                ulonglong2 A1 = *(const ulonglong2*)(ap + 4);  // tok pairs 2,3
                ulonglong2 B0 = *(const ulonglong2*)bp;        // code pairs 0,1
                ulonglong2 B1 = *(const ulonglong2*)(bp + 4);  // 2,3
                ulonglong2 B2 = *(const ulonglong2*)(bp + 8);  // 4,5
                ulonglong2 B3 = *(const ulonglong2*)(bp + 12); // 6,7
                unsigned long long pa[4] = {A0.x, A0.y, A1.x, A1.y};
                unsigned long long pb[8] = {B0.x, B0.y, B1.x, B1.y,
                                            B2.x, B2.y, B3.x, B3.y};
                #pragma unroll
                for (int i = 0; i < 4; ++i)
                    #pragma unroll
                    for (int j = 0; j < 8; ++j)
                        FMA2(acc[i][j], pa[i], pb[j]);
            }

            if (sl == 15) {
                // dot = even-dim sum + odd-dim sum; dist = fl(fl(rsq-2*dot)+csq)
                #pragma unroll
                for (int i = 0; i < 4; ++i) {
                    float rq = rsq[(tg << 2) + i];
                    #pragma unroll
                    for (int j = 0; j < 8; ++j) {
                        float lo = __uint_as_float((unsigned)acc[i][j]);
                        float hi = __uint_as_float((unsigned)(acc[i][j] >> 32));
                        float dot = lo + hi;
                        int code = kc + (cg << 3) + j;
                        float dist = fmaf(-2.f, dot, rq) + csql[code];
                        if (dist < bestv[i]) { bestv[i] = dist; besti[i] = code; }
                    }
                }
            }
        }

        // ---- cross-thread argmin reduce (lowest index wins ties)
        __syncthreads();
        #pragma unroll
        for (int i = 0; i < 4; ++i) {
            redv[cg * 64 + (tg << 2) + i] = bestv[i];
            redi[cg * 64 + (tg << 2) + i] = besti[i];
        }
        __syncthreads();
        if (tid < MT) {
            float bv = redv[tid]; int bi = redi[tid];
            #pragma unroll 1
            for (int c = 1; c < 16; ++c) {
                float v = redv[c * 64 + tid]; int ix = redi[c * 64 + tid];
                if (v < bv || (v == bv && ix < bi)) { bv = v; bi = ix; }
            }
            idxs[tid] = bi;
            out[IDXOFF + (size_t)(tok0 + tid) * QL + l] = (float)bi;
            atomicAdd(&g_cnt[l * KC + bi], 1);
        }
        __syncthreads();

        // ---- gather + residual/qsum update + rsq partials for next level
        {
            const int myidx = idxs[tloc];
            const float* qv = cbl + (size_t)myidx * DD + dbase;
            float* qs = g_qsum + (size_t)(tok0 + tloc) * DD + dbase;
            const float* xp = x + (size_t)(tok0 + tloc) * DD + dbase;
            float* op = out + (size_t)(tok0 + tloc) * DD + dbase;
            float s = 0.f;
            #pragma unroll 4
            for (int j = 0; j < 128; j += 4) {
                float4 q = *(const float4*)(qv + j);
                int dp = (dbase + j) >> 1;
                float2* p01 = (float2*)&res[dp * RP + tloc * 2];
                float2* p23 = (float2*)&res[(dp + 1) * RP + tloc * 2];
                float2 r01 = *p01, r23 = *p23;
                float r0 = r01.x - q.x, r1 = r01.y - q.y;
                float r2 = r23.x - q.z, r3 = r23.y - q.w;
                *p01 = make_float2(r0, r1);
                *p23 = make_float2(r2, r3);
                s += r0 * r0; s += r1 * r1; s += r2 * r2; s += r3 * r3;

                float4 qa;
                if (l == 0) {
                    qa = q;
                } else {
                    float4 o = *(const float4*)(qs + j);
                    qa.x = o.x + q.x; qa.y = o.y + q.y;
                    qa.z = o.z + q.z; qa.w = o.w + q.w;
                }
                *(float4*)(qs + j) = qa;

                if (l == QL - 1) {
                    float4 xv = *(const float4*)(xp + j);
                    float4 ov;
                    ov.x = xv.x + (qa.x - xv.x);
                    ov.y = xv.y + (qa.y - xv.y);
                    ov.z = xv.z + (qa.z - xv.z);
                    ov.w = xv.w + (qa.w - xv.w);
                    *(float4*)(op + j) = ov;
                }
            }
            rsqp[tsub * 64 + tloc] = s;
        }
        __syncthreads();
        if (tid < MT)
            rsq[tid] = ((rsqp[tid] + rsqp[64 + tid]) + rsqp[128 + tid]) + rsqp[192 + tid];
        __syncthreads();
        if (tid == 0) {
            double cs = 0.0;
            for (int t = 0; t < MT; ++t) cs += (double)rsq[t];
            atomicAdd(&g_commit[l], cs);
        }
    }
}

// ---------------------------------------------------------------------------
__global__ void rvq_fin(float* __restrict__ out) {
    __shared__ double red[256];
    const int tid = threadIdx.x;
    double psum = 0.0;
    for (int l = 0; l < QL; ++l) {
        double s = 0.0;
        for (int k = tid; k < KC; k += 256) {
            double p = (double)g_cnt[l * KC + k] / (double)NTOK;
            s += p * log(p + 1e-10);
        }
        red[tid] = s;
        __syncthreads();
        for (int off = 128; off > 0; off >>= 1) {
            if (tid < off) red[tid] += red[tid + off];
            __syncthreads();
        }
        if (tid == 0) psum += exp(-red[0]);
        __syncthreads();
    }
    if (tid == 0) {
        double closs = 0.0;
        for (int l = 0; l < QL; ++l)
            closs += g_commit[l] / ((double)NTOK * (double)DD);
        out[SCLOFF]     = (float)(0.25 * closs);
        out[SCLOFF + 1] = (float)(psum / (double)QL);
    }
}

// ---------------------------------------------------------------------------
extern "C" void kernel_launch(void* const* d_in, const int* in_sizes, int n_in,
                              void* d_out, int out_size) {
    const float* x  = (const float*)d_in[0];
    const float* cb = (const float*)d_in[1];
    float* out = (float*)d_out;

    const int smem = ((DD / 2) * RP + (DS / 2) * PSTR +
                      16 * 64 * 2 + 4 * 64 + 64 + 64) * 4;
    cudaFuncSetAttribute(rvq_main, cudaFuncAttributeMaxDynamicSharedMemorySize, smem);

    rvq_prep<<<(QL * KC + 255) / 256, 256>>>(cb);
    rvq_main<<<NCTA, 256, smem>>>(x, cb, out);
    rvq_fin<<<1, 256>>>(out);
}

// round 10
// speedup vs baseline: 1.0810x; 1.0783x over previous
#include <cuda_runtime.h>
#include <math.h>
#include <stdint.h>

// ---------------- problem constants ----------------
#define DD    512
#define KC    1024
#define QL    8
#define NTOK  16384
#define MTOK  128                  // tokens per GEMM CTA
#define NTL   128                  // codes per N-tile
#define KCH   32                   // dims per K-chunk
#define NITER 128                  // 8 ntiles * 16 chunks

#define IDXOFF ((size_t)NTOK * DD)
#define SCLOFF (IDXOFF + (size_t)NTOK * QL)

// ---------------- GEMM smem layout (bytes) ----------------
// per stage: Ahi[128][36f], Alo, Bhi[128][36f], Blo  (rows padded 128B->144B)
#define ARR_SZ   18432u            // 128 * 144
#define STG_SZ   73728u            // 4 arrays
#define OF_ALO   18432u
#define OF_BHI   36864u
#define OF_BLO   55296u
#define OF_CSQ   147456u
#define SMEM_GEMM (147456 + 4096)

// ---------------- device scratch (static; no cudaMalloc) ----------------
__device__ float  g_csq[QL * KC];
__device__ int    g_cnt[QL * KC];
__device__ double g_commit[QL];
__device__ int    g_top1[NTOK];
__device__ int    g_top2[NTOK];
__device__ float  g_rsq[NTOK];
__device__ float  g_res [(size_t)NTOK * DD];
__device__ float  g_qsum[(size_t)NTOK * DD];
__device__ float  g_rhi [(size_t)NTOK * DD];   // tf32-rounded residual hi
__device__ float  g_rlo [(size_t)NTOK * DD];   // tf32-rounded residual lo
__device__ float  g_cbhi[(size_t)QL * KC * DD];
__device__ float  g_cblo[(size_t)QL * KC * DD];

// ---------------- helpers ----------------
__device__ __forceinline__ uint32_t smem_u32(const void* p) {
    uint32_t a;
    asm("{ .reg .u64 t; cvta.to.shared.u64 t, %1; cvt.u32.u64 %0, t; }"
        : "=r"(a) : "l"(p));
    return a;
}
__device__ __forceinline__ float tf32r(float v) {
    float r; asm("cvt.rna.tf32.f32 %0, %1;" : "=f"(r) : "f"(v)); return r;
}
__device__ __forceinline__ void cpa16(uint32_t dst, const void* src) {
    asm volatile("cp.async.cg.shared.global [%0], [%1], 16;" :: "r"(dst), "l"(src));
}
#define CP_COMMIT() asm volatile("cp.async.commit_group;" ::: "memory")
#define CP_WAIT1()  asm volatile("cp.async.wait_group 1;" ::: "memory")
#define CP_WAIT0()  asm volatile("cp.async.wait_group 0;" ::: "memory")

#define LDSM4(r0, r1, r2, r3, a)                                               \
    asm volatile("ldmatrix.sync.aligned.m8n8.x4.shared.b16 {%0,%1,%2,%3}, [%4];" \
                 : "=r"(r0), "=r"(r1), "=r"(r2), "=r"(r3) : "r"(a))

#define MMA_TF32(c, a0, a1, a2, a3, b0, b1)                                    \
    asm volatile("mma.sync.aligned.m16n8k8.row.col.f32.tf32.tf32.f32 "         \
                 "{%0,%1,%2,%3}, {%4,%5,%6,%7}, {%8,%9}, {%0,%1,%2,%3};"       \
                 : "+f"((c)[0]), "+f"((c)[1]), "+f"((c)[2]), "+f"((c)[3])      \
                 : "r"(a0), "r"(a1), "r"(a2), "r"(a3), "r"(b0), "r"(b1))

// insert candidate (d,c) into per-lane top-2 (ascending c arrival)
#define TOP2_INS(v1, i1, v2, i2, d, c)                                         \
    do { if ((d) < (v1)) { v2 = v1; i2 = i1; v1 = (d); i1 = (c); }             \
         else if ((d) < (v2)) { v2 = (d); i2 = (c); } } while (0)

// merge top-2 pairs across lanes (xor off); lex order (value, index)
__device__ __forceinline__ void top2_merge(float& v1, int& i1,
                                           float& v2, int& i2, int off) {
    float w1 = __shfl_xor_sync(0xffffffffu, v1, off);
    int   j1 = __shfl_xor_sync(0xffffffffu, i1, off);
    float w2 = __shfl_xor_sync(0xffffffffu, v2, off);
    int   j2 = __shfl_xor_sync(0xffffffffu, i2, off);
    if (w1 < v1 || (w1 == v1 && j1 < i1)) {
        if (v1 < w2 || (v1 == w2 && i1 < j2)) { v2 = v1; i2 = i1; }
        else                                  { v2 = w2; i2 = j2; }
        v1 = w1; i1 = j1;
    } else {
        if (w1 < v2 || (w1 == v2 && j1 < i2)) { v2 = w1; i2 = j1; }
    }
}

// ---------------------------------------------------------------------------
// prep: csq (fp32 sequential sum — matches passing kernel), zero stats
// ---------------------------------------------------------------------------
__global__ void rvq_prep(const float* __restrict__ cb) {
    int i = blockIdx.x * blockDim.x + threadIdx.x;
    if (i < QL * KC) {
        const float* c = cb + (size_t)i * DD;
        float s = 0.f;
        for (int d = 0; d < DD; ++d) { float v = c[d]; s += v * v; }
        g_csq[i] = s;
        g_cnt[i] = 0;
    }
    if (i < QL) g_commit[i] = 0.0;
}

// codebook fp32 -> tf32 hi/lo
__global__ void rvq_cbconv(const float* __restrict__ cb) {
    size_t i = ((size_t)blockIdx.x * blockDim.x + threadIdx.x) * 4;
    if (i >= (size_t)QL * KC * DD) return;
    float4 v = *(const float4*)(cb + i);
    float4 h, lo;
    h.x = tf32r(v.x); lo.x = tf32r(v.x - h.x);
    h.y = tf32r(v.y); lo.y = tf32r(v.y - h.y);
    h.z = tf32r(v.z); lo.z = tf32r(v.z - h.z);
    h.w = tf32r(v.w); lo.w = tf32r(v.w - h.w);
    *(float4*)(g_cbhi + i) = h;
    *(float4*)(g_cblo + i) = lo;
}

// init: x -> rhi/rlo + rsq (exact partial scheme of the passing kernel)
__global__ void rvq_init(const float* __restrict__ x) {
    __shared__ float rsqp[4 * 64];
    const int tid  = threadIdx.x;
    const int tsub = tid & 3, tloc = tid >> 2, dbase = tsub * 128;
    const int tok  = blockIdx.x * 64 + tloc;
    const float* xp = x + (size_t)tok * DD + dbase;
    float* hp = g_rhi + (size_t)tok * DD + dbase;
    float* lp = g_rlo + (size_t)tok * DD + dbase;
    float s = 0.f;
    #pragma unroll 4
    for (int j = 0; j < 128; j += 4) {
        float4 v = *(const float4*)(xp + j);
        float4 h, lo;
        s += v.x * v.x; s += v.y * v.y; s += v.z * v.z; s += v.w * v.w;
        h.x = tf32r(v.x); lo.x = tf32r(v.x - h.x);
        h.y = tf32r(v.y); lo.y = tf32r(v.y - h.y);
        h.z = tf32r(v.z); lo.z = tf32r(v.z - h.z);
        h.w = tf32r(v.w); lo.w = tf32r(v.w - h.w);
        *(float4*)(hp + j) = h;
        *(float4*)(lp + j) = lo;
    }
    rsqp[tsub * 64 + tloc] = s;
    __syncthreads();
    if (tid < 64)
        g_rsq[blockIdx.x * 64 + tid] =
            ((rsqp[tid] + rsqp[64 + tid]) + rsqp[128 + tid]) + rsqp[192 + tid];
}

// ---------------------------------------------------------------------------
// GEMM: mma.sync tf32 3-pass split; epilogue nominates TOP-2 codes per token
// ---------------------------------------------------------------------------
__global__ void __launch_bounds__(256, 1)
rvq_gemm(int l) {
    extern __shared__ char sm[];
    const uint32_t sb = smem_u32(sm);
    float* csq_sm = (float*)(sm + OF_CSQ);

    const int tid  = threadIdx.x;
    const int wid  = tid >> 5;
    const int lane = tid & 31;
    const int tok0 = blockIdx.x * MTOK;

    for (int i = tid; i < KC; i += 256) csq_sm[i] = g_csq[l * KC + i];

    const int row0 = wid * 16 + (lane >> 2);
    const int row1 = row0 + 8;
    const float rsq0 = g_rsq[tok0 + row0];
    const float rsq1 = g_rsq[tok0 + row1];

    // ldmatrix source offsets (within each array)
    const uint32_t lrow = lane & 15;
    const uint32_t acol = (uint32_t)((lane >> 4) << 4);
    const uint32_t aoff = (uint32_t)(wid * 16 + lrow) * 144u + acol;
    const uint32_t boff = lrow * 144u + acol;

    const float* Ahi0 = g_rhi + (size_t)tok0 * DD;
    const float* Alo0 = g_rlo + (size_t)tok0 * DD;
    const float* Bhi0 = g_cbhi + (size_t)l * KC * DD;
    const float* Blo0 = g_cblo + (size_t)l * KC * DD;

    const float INF = __int_as_float(0x7f800000);
    float bv0 = INF, bv0b = INF, bv1 = INF, bv1b = INF;
    int   bi0 = 0,   bi0b = 0,   bi1 = 0,   bi1b = 0;

    float acc[16][4];

    // cp.async issue for iteration `it` (ntile = it>>4, chunk = it&15)
    auto issue = [&](int it) {
        const int ntb = (it >> 4) * NTL;
        const int d0  = (it & 15) * KCH;
        const uint32_t st = sb + (uint32_t)(it & 1) * STG_SZ;
        const float* Ah = Ahi0 + d0;
        const float* Al = Alo0 + d0;
        const float* Bh = Bhi0 + (size_t)ntb * DD + d0;
        const float* Bl = Blo0 + (size_t)ntb * DD + d0;
        #pragma unroll
        for (int i = 0; i < 4; ++i) {
            int gi = i * 256 + tid;
            int r  = gi >> 3, g = gi & 7;
            uint32_t doff = (uint32_t)r * 144u + (uint32_t)g * 16u;
            size_t   soff = (size_t)r * DD + g * 4;
            cpa16(st + doff,          Ah + soff);
            cpa16(st + OF_ALO + doff, Al + soff);
            cpa16(st + OF_BHI + doff, Bh + soff);
            cpa16(st + OF_BLO + doff, Bl + soff);
        }
    };

    issue(0);
    CP_COMMIT();

    #pragma unroll 1
    for (int it = 0; it < NITER; ++it) {
        if (it + 1 < NITER) { issue(it + 1); CP_COMMIT(); CP_WAIT1(); }
        else                { CP_WAIT0(); }
        __syncthreads();

        if ((it & 15) == 0) {
            #pragma unroll
            for (int t = 0; t < 16; ++t)
                #pragma unroll
                for (int k = 0; k < 4; ++k) acc[t][k] = 0.f;
        }

        const uint32_t stage = sb + (uint32_t)(it & 1) * STG_SZ;
        #pragma unroll
        for (int pass = 0; pass < 3; ++pass) {
            const uint32_t Ab = stage + (pass == 2 ? OF_ALO : 0u);
            const uint32_t Bb = stage + (pass == 1 ? OF_BLO : OF_BHI);
            #pragma unroll
            for (int ks = 0; ks < 4; ++ks) {
                uint32_t a0, a1, a2, a3;
                LDSM4(a0, a1, a2, a3, Ab + aoff + (uint32_t)ks * 32u);
                #pragma unroll
                for (int cg = 0; cg < 8; ++cg) {
                    uint32_t b0, b1, b2, b3;
                    LDSM4(b0, b1, b2, b3,
                          Bb + boff + (uint32_t)cg * (16u * 144u) + (uint32_t)ks * 32u);
                    // n-group 0 uses (m0 = n0-7/k0-3, m2 = n0-7/k4-7); group 1 (m1, m3)
                    MMA_TF32(acc[cg * 2],     a0, a1, a2, a3, b0, b2);
                    MMA_TF32(acc[cg * 2 + 1], a0, a1, a2, a3, b1, b3);
                }
            }
        }

        if ((it & 15) == 15) {
            // epilogue for ntile it>>4: dist + running top-2 (ascending codes)
            const int ntb = (it >> 4) * NTL;
            #pragma unroll
            for (int nt = 0; nt < 16; ++nt) {
                int c0 = ntb + nt * 8 + 2 * (lane & 3);
                float q0 = csq_sm[c0], q1 = csq_sm[c0 + 1];
                float d00 = fmaf(-2.f, acc[nt][0], rsq0) + q0;
                float d01 = fmaf(-2.f, acc[nt][1], rsq0) + q1;
                float d10 = fmaf(-2.f, acc[nt][2], rsq1) + q0;
                float d11 = fmaf(-2.f, acc[nt][3], rsq1) + q1;
                TOP2_INS(bv0, bi0, bv0b, bi0b, d00, c0);
                TOP2_INS(bv0, bi0, bv0b, bi0b, d01, c0 + 1);
                TOP2_INS(bv1, bi1, bv1b, bi1b, d10, c0);
                TOP2_INS(bv1, bi1, bv1b, bi1b, d11, c0 + 1);
            }
        }
        __syncthreads();
    }

    // merge top-2 across the 4 lanes sharing each row (disjoint candidates)
    top2_merge(bv0, bi0, bv0b, bi0b, 1);
    top2_merge(bv0, bi0, bv0b, bi0b, 2);
    top2_merge(bv1, bi1, bv1b, bi1b, 1);
    top2_merge(bv1, bi1, bv1b, bi1b, 2);
    if ((lane & 3) == 0) {
        g_top1[tok0 + row0] = bi0;  g_top2[tok0 + row0] = bi0b;
        g_top1[tok0 + row1] = bi1;  g_top2[tok0 + row1] = bi1b;
    }
}

// ---------------------------------------------------------------------------
// update: EXACT fp32 rescore of the two nominated codes (decides argmin with
// the proven scalar chain), then gather + residual/qsum update (exact fp32),
// next-level tf32 hi/lo, rsq, commit, counts, index output.
// ---------------------------------------------------------------------------
__global__ void __launch_bounds__(256)
rvq_update(int l, const float* __restrict__ x, const float* __restrict__ cb,
           float* __restrict__ out) {
    __shared__ float dotp[2][4][64];
    __shared__ int   widx[64];
    __shared__ float rsqp[4 * 64];
    __shared__ float rsqs[64];
    const int tid  = threadIdx.x;
    const int tsub = tid & 3, tloc = tid >> 2, dbase = tsub * 128;
    const int tok0 = blockIdx.x * 64;
    const int tok  = tok0 + tloc;

    const float* rp = (l == 0 ? x : g_res) + (size_t)tok * DD + dbase;

    // ---- rescore phase: exact fp32 dots for both candidates
    {
        const int cA = g_top1[tok];
        const int cB = g_top2[tok];
        const float* bA = cb + ((size_t)l * KC + cA) * DD + dbase;
        const float* bB = cb + ((size_t)l * KC + cB) * DD + dbase;
        float pA = 0.f, pB = 0.f;
        #pragma unroll 4
        for (int j = 0; j < 128; j += 4) {
            float4 r = *(const float4*)(rp + j);
            float4 a = *(const float4*)(bA + j);
            float4 b = *(const float4*)(bB + j);
            pA = fmaf(r.x, a.x, pA); pA = fmaf(r.y, a.y, pA);
            pA = fmaf(r.z, a.z, pA); pA = fmaf(r.w, a.w, pA);
            pB = fmaf(r.x, b.x, pB); pB = fmaf(r.y, b.y, pB);
            pB = fmaf(r.z, b.z, pB); pB = fmaf(r.w, b.w, pB);
        }
        dotp[0][tsub][tloc] = pA;
        dotp[1][tsub][tloc] = pB;
        __syncthreads();
        if (tsub == 0) {
            float dotA = ((dotp[0][0][tloc] + dotp[0][1][tloc])
                          + dotp[0][2][tloc]) + dotp[0][3][tloc];
            float dotB = ((dotp[1][0][tloc] + dotp[1][1][tloc])
                          + dotp[1][2][tloc]) + dotp[1][3][tloc];
            float rq = g_rsq[tok];
            float dA = fmaf(-2.f, dotA, rq) + g_csq[l * KC + cA];
            float dB = fmaf(-2.f, dotB, rq) + g_csq[l * KC + cB];
            int win = (dB < dA || (dB == dA && cB < cA)) ? cB : cA;
            widx[tloc] = win;
            out[IDXOFF + (size_t)tok * QL + l] = (float)win;
            atomicAdd(&g_cnt[l * KC + win], 1);
        }
        __syncthreads();
    }

    const int idx = widx[tloc];
    const float* qv = cb + ((size_t)l * KC + idx) * DD + dbase;
    float* rw = g_res + (size_t)tok * DD + dbase;
    float* qs = g_qsum + (size_t)tok * DD + dbase;
    const float* xp = x + (size_t)tok * DD + dbase;
    float* op = out + (size_t)tok * DD + dbase;
    float* hp = g_rhi + (size_t)tok * DD + dbase;
    float* lp = g_rlo + (size_t)tok * DD + dbase;

    float s = 0.f;
    #pragma unroll 4
    for (int j = 0; j < 128; j += 4) {
        float4 r = *(const float4*)(rp + j);
        float4 q = *(const float4*)(qv + j);
        float4 rn = make_float4(r.x - q.x, r.y - q.y, r.z - q.z, r.w - q.w);
        *(float4*)(rw + j) = rn;
        s += rn.x * rn.x; s += rn.y * rn.y; s += rn.z * rn.z; s += rn.w * rn.w;
        if (l < QL - 1) {
            float4 h, lo;
            h.x = tf32r(rn.x); lo.x = tf32r(rn.x - h.x);
            h.y = tf32r(rn.y); lo.y = tf32r(rn.y - h.y);
            h.z = tf32r(rn.z); lo.z = tf32r(rn.z - h.z);
            h.w = tf32r(rn.w); lo.w = tf32r(rn.w - h.w);
            *(float4*)(hp + j) = h;
            *(float4*)(lp + j) = lo;
        }

        float4 qa;
        if (l == 0) {
            qa = q;
        } else {
            float4 o = *(const float4*)(qs + j);
            qa.x = o.x + q.x; qa.y = o.y + q.y;
            qa.z = o.z + q.z; qa.w = o.w + q.w;
        }
        *(float4*)(qs + j) = qa;

        if (l == QL - 1) {
            float4 xv = *(const float4*)(xp + j);
            float4 ov;
            ov.x = xv.x + (qa.x - xv.x);
            ov.y = xv.y + (qa.y - xv.y);
            ov.z = xv.z + (qa.z - xv.z);
            ov.w = xv.w + (qa.w - xv.w);
            *(float4*)(op + j) = ov;
        }
    }
    rsqp[tsub * 64 + tloc] = s;
    __syncthreads();
    if (tid < 64) {
        float r = ((rsqp[tid] + rsqp[64 + tid]) + rsqp[128 + tid]) + rsqp[192 + tid];
        g_rsq[tok0 + tid] = r;
        rsqs[tid] = r;
    }
    __syncthreads();
    if (tid == 0) {
        double cs = 0.0;
        for (int t = 0; t < 64; ++t) cs += (double)rsqs[t];
        atomicAdd(&g_commit[l], cs);
    }
}

// ---------------------------------------------------------------------------
__global__ void rvq_fin(float* __restrict__ out) {
    __shared__ double red[256];
    const int tid = threadIdx.x;
    double psum = 0.0;
    for (int l = 0; l < QL; ++l) {
        double s = 0.0;
        for (int k = tid; k < KC; k += 256) {
            double p = (double)g_cnt[l * KC + k] / (double)NTOK;
            s += p * log(p + 1e-10);
        }
        red[tid] = s;
        __syncthreads();
        for (int off = 128; off > 0; off >>= 1) {
            if (tid < off) red[tid] += red[tid + off];
            __syncthreads();
        }
        if (tid == 0) psum += exp(-red[0]);
        __syncthreads();
    }
    if (tid == 0) {
        double closs = 0.0;
        for (int l = 0; l < QL; ++l)
            closs += g_commit[l] / ((double)NTOK * (double)DD);
        out[SCLOFF]     = (float)(0.25 * closs);
        out[SCLOFF + 1] = (float)(psum / (double)QL);
    }
}

// ---------------------------------------------------------------------------
extern "C" void kernel_launch(void* const* d_in, const int* in_sizes, int n_in,
                              void* d_out, int out_size) {
    const float* x  = (const float*)d_in[0];
    const float* cb = (const float*)d_in[1];
    float* out = (float*)d_out;

    cudaFuncSetAttribute(rvq_gemm, cudaFuncAttributeMaxDynamicSharedMemorySize,
                         SMEM_GEMM);

    rvq_prep<<<(QL * KC + 255) / 256, 256>>>(cb);
    rvq_cbconv<<<(int)(((size_t)QL * KC * DD / 4 + 255) / 256), 256>>>(cb);
    rvq_init<<<NTOK / 64, 256>>>(x);
    for (int l = 0; l < QL; ++l) {
        rvq_gemm<<<NTOK / MTOK, 256, SMEM_GEMM>>>(l);
        rvq_update<<<NTOK / 64, 256>>>(l, x, cb, out);
    }
    rvq_fin<<<1, 256>>>(out);
}

// round 11
// speedup vs baseline: 1.5510x; 1.4348x over previous
#include <cuda_runtime.h>
#include <cuda_bf16.h>
#include <math.h>
#include <stdint.h>

// ---------------- problem constants ----------------
#define DD    512
#define KC    1024
#define QL    8
#define NTOK  16384
#define MTOK  128                  // tokens per GEMM CTA
#define NTL   128                  // codes per N-tile
#define KCH   32                   // dims per K-chunk
#define NITER 128                  // 8 ntiles * 16 chunks

#define IDXOFF ((size_t)NTOK * DD)
#define SCLOFF (IDXOFF + (size_t)NTOK * QL)

// ---------------- GEMM smem layout (bytes) ----------------
// per stage: Ahi[128 rows][80B], Alo, Bhi[128][80B], Blo  (64B data + 16B pad)
#define RSTRB  80u
#define MAT_SZ 10240u              // 128 * 80
#define OF_ALO 10240u
#define OF_BHI 20480u
#define OF_BLO 30720u
#define STG_SZ 40960u
#define NSTG   3
#define OF_CSQ 122880u
#define SMEM_GEMM (122880 + 4096)

// ---------------- device scratch (static; no cudaMalloc) ----------------
__device__ float          g_csq[QL * KC];
__device__ int            g_cnt[QL * KC];
__device__ double         g_commit[QL];
__device__ int            g_top1[NTOK];
__device__ int            g_top2[NTOK];
__device__ float          g_rsq[NTOK];
__device__ float          g_res [(size_t)NTOK * DD];
__device__ float          g_qsum[(size_t)NTOK * DD];
__device__ __nv_bfloat16  g_rhi [(size_t)NTOK * DD];
__device__ __nv_bfloat16  g_rlo [(size_t)NTOK * DD];
__device__ __nv_bfloat16  g_cbhi[(size_t)QL * KC * DD];
__device__ __nv_bfloat16  g_cblo[(size_t)QL * KC * DD];

// ---------------- helpers ----------------
__device__ __forceinline__ uint32_t smem_u32(const void* p) {
    uint32_t a;
    asm("{ .reg .u64 t; cvta.to.shared.u64 t, %1; cvt.u32.u64 %0, t; }"
        : "=r"(a) : "l"(p));
    return a;
}
__device__ __forceinline__ void cpa16(uint32_t dst, const void* src) {
    asm volatile("cp.async.cg.shared.global [%0], [%1], 16;" :: "r"(dst), "l"(src));
}
#define CP_COMMIT() asm volatile("cp.async.commit_group;" ::: "memory")
#define CP_WAIT2()  asm volatile("cp.async.wait_group 2;" ::: "memory")
#define CP_WAIT1()  asm volatile("cp.async.wait_group 1;" ::: "memory")
#define CP_WAIT0()  asm volatile("cp.async.wait_group 0;" ::: "memory")

#define LDSM4(r0, r1, r2, r3, a)                                               \
    asm volatile("ldmatrix.sync.aligned.m8n8.x4.shared.b16 {%0,%1,%2,%3}, [%4];" \
                 : "=r"(r0), "=r"(r1), "=r"(r2), "=r"(r3) : "r"(a))

#define MMA_BF16(c, a0, a1, a2, a3, b0, b1)                                    \
    asm volatile("mma.sync.aligned.m16n8k16.row.col.f32.bf16.bf16.f32 "        \
                 "{%0,%1,%2,%3}, {%4,%5,%6,%7}, {%8,%9}, {%0,%1,%2,%3};"       \
                 : "+f"((c)[0]), "+f"((c)[1]), "+f"((c)[2]), "+f"((c)[3])      \
                 : "r"(a0), "r"(a1), "r"(a2), "r"(a3), "r"(b0), "r"(b1))

// insert candidate (d,c) into per-lane top-2 (ascending c arrival)
#define TOP2_INS(v1, i1, v2, i2, d, c)                                         \
    do { if ((d) < (v1)) { v2 = v1; i2 = i1; v1 = (d); i1 = (c); }             \
         else if ((d) < (v2)) { v2 = (d); i2 = (c); } } while (0)

// merge top-2 pairs across lanes (xor off); lex order (value, index)
__device__ __forceinline__ void top2_merge(float& v1, int& i1,
                                           float& v2, int& i2, int off) {
    float w1 = __shfl_xor_sync(0xffffffffu, v1, off);
    int   j1 = __shfl_xor_sync(0xffffffffu, i1, off);
    float w2 = __shfl_xor_sync(0xffffffffu, v2, off);
    int   j2 = __shfl_xor_sync(0xffffffffu, i2, off);
    if (w1 < v1 || (w1 == v1 && j1 < i1)) {
        if (v1 < w2 || (v1 == w2 && i1 < j2)) { v2 = v1; i2 = i1; }
        else                                  { v2 = w2; i2 = j2; }
        v1 = w1; i1 = j1;
    } else {
        if (w1 < v2 || (w1 == v2 && j1 < i2)) { v2 = w1; i2 = j1; }
    }
}

// ---------------------------------------------------------------------------
// prep: csq (fp32 sequential sum — matches passing kernel), zero stats
// ---------------------------------------------------------------------------
__global__ void rvq_prep(const float* __restrict__ cb) {
    int i = blockIdx.x * blockDim.x + threadIdx.x;
    if (i < QL * KC) {
        const float* c = cb + (size_t)i * DD;
        float s = 0.f;
        for (int d = 0; d < DD; ++d) { float v = c[d]; s += v * v; }
        g_csq[i] = s;
        g_cnt[i] = 0;
    }
    if (i < QL) g_commit[i] = 0.0;
}

// codebook fp32 -> bf16 hi/lo
__global__ void rvq_cbconv(const float* __restrict__ cb) {
    size_t i = ((size_t)blockIdx.x * blockDim.x + threadIdx.x) * 4;
    if (i >= (size_t)QL * KC * DD) return;
    float4 v = *(const float4*)(cb + i);
    float vv[4] = {v.x, v.y, v.z, v.w};
    __nv_bfloat16 h[4], lo[4];
    #pragma unroll
    for (int k = 0; k < 4; ++k) {
        h[k]  = __float2bfloat16(vv[k]);
        lo[k] = __float2bfloat16(vv[k] - __bfloat162float(h[k]));
    }
    *(__nv_bfloat162*)(g_cbhi + i)     = __nv_bfloat162(h[0], h[1]);
    *(__nv_bfloat162*)(g_cbhi + i + 2) = __nv_bfloat162(h[2], h[3]);
    *(__nv_bfloat162*)(g_cblo + i)     = __nv_bfloat162(lo[0], lo[1]);
    *(__nv_bfloat162*)(g_cblo + i + 2) = __nv_bfloat162(lo[2], lo[3]);
}

// init: x -> rhi/rlo (bf16) + rsq (exact partial scheme of the passing kernel)
__global__ void rvq_init(const float* __restrict__ x) {
    __shared__ float rsqp[4 * 64];
    const int tid  = threadIdx.x;
    const int tsub = tid & 3, tloc = tid >> 2, dbase = tsub * 128;
    const int tok  = blockIdx.x * 64 + tloc;
    const float* xp = x + (size_t)tok * DD + dbase;
    __nv_bfloat16* hp = g_rhi + (size_t)tok * DD + dbase;
    __nv_bfloat16* lp = g_rlo + (size_t)tok * DD + dbase;
    float s = 0.f;
    #pragma unroll 4
    for (int j = 0; j < 128; j += 4) {
        float4 v = *(const float4*)(xp + j);
        float vv[4] = {v.x, v.y, v.z, v.w};
        __nv_bfloat16 h[4], lo[4];
        #pragma unroll
        for (int k = 0; k < 4; ++k) {
            s += vv[k] * vv[k];
            h[k]  = __float2bfloat16(vv[k]);
            lo[k] = __float2bfloat16(vv[k] - __bfloat162float(h[k]));
        }
        *(__nv_bfloat162*)(hp + j)     = __nv_bfloat162(h[0], h[1]);
        *(__nv_bfloat162*)(hp + j + 2) = __nv_bfloat162(h[2], h[3]);
        *(__nv_bfloat162*)(lp + j)     = __nv_bfloat162(lo[0], lo[1]);
        *(__nv_bfloat162*)(lp + j + 2) = __nv_bfloat162(lo[2], lo[3]);
    }
    rsqp[tsub * 64 + tloc] = s;
    __syncthreads();
    if (tid < 64)
        g_rsq[blockIdx.x * 64 + tid] =
            ((rsqp[tid] + rsqp[64 + tid]) + rsqp[128 + tid]) + rsqp[192 + tid];
}

// ---------------------------------------------------------------------------
// GEMM: bf16 m16n8k16, 3-term hi/lo split with fragment reuse;
// epilogue nominates TOP-2 codes per token (exact rescore decides later).
// ---------------------------------------------------------------------------
__global__ void __launch_bounds__(256, 1)
rvq_gemm(int l) {
    extern __shared__ char sm[];
    const uint32_t sb = smem_u32(sm);
    float* csq_sm = (float*)(sm + OF_CSQ);

    const int tid  = threadIdx.x;
    const int wid  = tid >> 5;
    const int lane = tid & 31;
    const int tok0 = blockIdx.x * MTOK;

    for (int i = tid; i < KC; i += 256) csq_sm[i] = g_csq[l * KC + i];

    const int row0 = wid * 16 + (lane >> 2);
    const int row1 = row0 + 8;
    const float rsq0 = g_rsq[tok0 + row0];
    const float rsq1 = g_rsq[tok0 + row1];

    // ldmatrix source offsets: lanes 0-15 -> rows, lanes 16-31 -> rows at +16B
    const uint32_t lrow = lane & 15;
    const uint32_t acol = (uint32_t)((lane >> 4) << 4);
    const uint32_t aoff = (uint32_t)(wid * 16 + lrow) * RSTRB + acol;
    const uint32_t boff = lrow * RSTRB + acol;

    const __nv_bfloat16* Ahi0 = g_rhi + (size_t)tok0 * DD;
    const __nv_bfloat16* Alo0 = g_rlo + (size_t)tok0 * DD;
    const __nv_bfloat16* Bhi0 = g_cbhi + (size_t)l * KC * DD;
    const __nv_bfloat16* Blo0 = g_cblo + (size_t)l * KC * DD;

    const float INF = __int_as_float(0x7f800000);
    float bv0 = INF, bv0b = INF, bv1 = INF, bv1b = INF;
    int   bi0 = 0,   bi0b = 0,   bi1 = 0,   bi1b = 0;

    float acc[16][4];

    // cp.async issue for iteration `it` (ntile = it>>4, chunk = it&15)
    auto issue = [&](int it) {
        const int ntb = (it >> 4) * NTL;
        const int d0  = (it & 15) * KCH;
        const uint32_t st = sb + (uint32_t)(it % NSTG) * STG_SZ;
        const __nv_bfloat16* Ah = Ahi0 + d0;
        const __nv_bfloat16* Al = Alo0 + d0;
        const __nv_bfloat16* Bh = Bhi0 + (size_t)ntb * DD + d0;
        const __nv_bfloat16* Bl = Blo0 + (size_t)ntb * DD + d0;
        #pragma unroll
        for (int i = 0; i < 2; ++i) {
            int gi = i * 256 + tid;          // 512 granules of 16B per array
            int r  = gi >> 2, g = gi & 3;
            uint32_t doff = (uint32_t)r * RSTRB + (uint32_t)g * 16u;
            size_t   soff = (size_t)r * DD + g * 8;
            cpa16(st + doff,          Ah + soff);
            cpa16(st + OF_ALO + doff, Al + soff);
            cpa16(st + OF_BHI + doff, Bh + soff);
            cpa16(st + OF_BLO + doff, Bl + soff);
        }
    };

    issue(0); CP_COMMIT();
    issue(1); CP_COMMIT();

    #pragma unroll 1
    for (int it = 0; it < NITER; ++it) {
        if (it + 2 < NITER) { issue(it + 2); CP_COMMIT(); CP_WAIT2(); }
        else if (it + 1 < NITER) { CP_WAIT1(); }
        else { CP_WAIT0(); }
        __syncthreads();

        if ((it & 15) == 0) {
            #pragma unroll
            for (int t = 0; t < 16; ++t)
                #pragma unroll
                for (int k = 0; k < 4; ++k) acc[t][k] = 0.f;
        }

        const uint32_t stage = sb + (uint32_t)(it % NSTG) * STG_SZ;
        #pragma unroll
        for (int ks = 0; ks < 2; ++ks) {
            // A fragments (hi reused by 2 terms, lo by 1)
            uint32_t ah0, ah1, ah2, ah3, al0, al1, al2, al3;
            LDSM4(ah0, ah1, ah2, ah3, stage + aoff + (uint32_t)ks * 32u);
            LDSM4(al0, al1, al2, al3, stage + OF_ALO + aoff + (uint32_t)ks * 32u);
            #pragma unroll
            for (int cg = 0; cg < 8; ++cg) {
                const uint32_t bo = boff + (uint32_t)cg * (16u * RSTRB)
                                         + (uint32_t)ks * 32u;
                uint32_t bh0, bh1, bh2, bh3, bl0, bl1, bl2, bl3;
                LDSM4(bh0, bh1, bh2, bh3, stage + OF_BHI + bo);
                LDSM4(bl0, bl1, bl2, bl3, stage + OF_BLO + bo);
                // n-group0 uses (m0=n0-7/k0-7, m2=n0-7/k8-15); group1 (m1, m3)
                MMA_BF16(acc[cg * 2],     ah0, ah1, ah2, ah3, bh0, bh2); // hi*hi
                MMA_BF16(acc[cg * 2 + 1], ah0, ah1, ah2, ah3, bh1, bh3);
                MMA_BF16(acc[cg * 2],     ah0, ah1, ah2, ah3, bl0, bl2); // hi*lo
                MMA_BF16(acc[cg * 2 + 1], ah0, ah1, ah2, ah3, bl1, bl3);
                MMA_BF16(acc[cg * 2],     al0, al1, al2, al3, bh0, bh2); // lo*hi
                MMA_BF16(acc[cg * 2 + 1], al0, al1, al2, al3, bh1, bh3);
            }
        }

        if ((it & 15) == 15) {
            // epilogue for ntile it>>4: dist + running top-2 (ascending codes)
            const int ntb = (it >> 4) * NTL;
            #pragma unroll
            for (int nt = 0; nt < 16; ++nt) {
                int c0 = ntb + nt * 8 + 2 * (lane & 3);
                float q0 = csq_sm[c0], q1 = csq_sm[c0 + 1];
                float d00 = fmaf(-2.f, acc[nt][0], rsq0) + q0;
                float d01 = fmaf(-2.f, acc[nt][1], rsq0) + q1;
                float d10 = fmaf(-2.f, acc[nt][2], rsq1) + q0;
                float d11 = fmaf(-2.f, acc[nt][3], rsq1) + q1;
                TOP2_INS(bv0, bi0, bv0b, bi0b, d00, c0);
                TOP2_INS(bv0, bi0, bv0b, bi0b, d01, c0 + 1);
                TOP2_INS(bv1, bi1, bv1b, bi1b, d10, c0);
                TOP2_INS(bv1, bi1, bv1b, bi1b, d11, c0 + 1);
            }
        }
        __syncthreads();
    }

    // merge top-2 across the 4 lanes sharing each row (disjoint candidates)
    top2_merge(bv0, bi0, bv0b, bi0b, 1);
    top2_merge(bv0, bi0, bv0b, bi0b, 2);
    top2_merge(bv1, bi1, bv1b, bi1b, 1);
    top2_merge(bv1, bi1, bv1b, bi1b, 2);
    if ((lane & 3) == 0) {
        g_top1[tok0 + row0] = bi0;  g_top2[tok0 + row0] = bi0b;
        g_top1[tok0 + row1] = bi1;  g_top2[tok0 + row1] = bi1b;
    }
}

// ---------------------------------------------------------------------------
// update: EXACT fp32 rescore of the two nominated codes (proven scalar chain
// decides argmin), then gather + residual/qsum update (exact fp32),
// next-level bf16 hi/lo, rsq, commit, counts, index output.
// ---------------------------------------------------------------------------
__global__ void __launch_bounds__(256)
rvq_update(int l, const float* __restrict__ x, const float* __restrict__ cb,
           float* __restrict__ out) {
    __shared__ float dotp[2][4][64];
    __shared__ int   widx[64];
    __shared__ float rsqp[4 * 64];
    __shared__ float rsqs[64];
    const int tid  = threadIdx.x;
    const int tsub = tid & 3, tloc = tid >> 2, dbase = tsub * 128;
    const int tok0 = blockIdx.x * 64;
    const int tok  = tok0 + tloc;

    const float* rp = (l == 0 ? x : g_res) + (size_t)tok * DD + dbase;

    // ---- rescore phase: exact fp32 dots for both candidates
    {
        const int cA = g_top1[tok];
        const int cB = g_top2[tok];
        const float* bA = cb + ((size_t)l * KC + cA) * DD + dbase;
        const float* bB = cb + ((size_t)l * KC + cB) * DD + dbase;
        float pA = 0.f, pB = 0.f;
        #pragma unroll 4
        for (int j = 0; j < 128; j += 4) {
            float4 r = *(const float4*)(rp + j);
            float4 a = *(const float4*)(bA + j);
            float4 b = *(const float4*)(bB + j);
            pA = fmaf(r.x, a.x, pA); pA = fmaf(r.y, a.y, pA);
            pA = fmaf(r.z, a.z, pA); pA = fmaf(r.w, a.w, pA);
            pB = fmaf(r.x, b.x, pB); pB = fmaf(r.y, b.y, pB);
            pB = fmaf(r.z, b.z, pB); pB = fmaf(r.w, b.w, pB);
        }
        dotp[0][tsub][tloc] = pA;
        dotp[1][tsub][tloc] = pB;
        __syncthreads();
        if (tsub == 0) {
            float dotA = ((dotp[0][0][tloc] + dotp[0][1][tloc])
                          + dotp[0][2][tloc]) + dotp[0][3][tloc];
            float dotB = ((dotp[1][0][tloc] + dotp[1][1][tloc])
                          + dotp[1][2][tloc]) + dotp[1][3][tloc];
            float rq = g_rsq[tok];
            float dA = fmaf(-2.f, dotA, rq) + g_csq[l * KC + cA];
            float dB = fmaf(-2.f, dotB, rq) + g_csq[l * KC + cB];
            int win = (dB < dA || (dB == dA && cB < cA)) ? cB : cA;
            widx[tloc] = win;
            out[IDXOFF + (size_t)tok * QL + l] = (float)win;
            atomicAdd(&g_cnt[l * KC + win], 1);
        }
        __syncthreads();
    }

    const int idx = widx[tloc];
    const float* qv = cb + ((size_t)l * KC + idx) * DD + dbase;
    float* rw = g_res + (size_t)tok * DD + dbase;
    float* qs = g_qsum + (size_t)tok * DD + dbase;
    const float* xp = x + (size_t)tok * DD + dbase;
    float* op = out + (size_t)tok * DD + dbase;
    __nv_bfloat16* hp = g_rhi + (size_t)tok * DD + dbase;
    __nv_bfloat16* lp = g_rlo + (size_t)tok * DD + dbase;

    float s = 0.f;
    #pragma unroll 4
    for (int j = 0; j < 128; j += 4) {
        float4 r = *(const float4*)(rp + j);
        float4 q = *(const float4*)(qv + j);
        float rn[4] = {r.x - q.x, r.y - q.y, r.z - q.z, r.w - q.w};
        *(float4*)(rw + j) = make_float4(rn[0], rn[1], rn[2], rn[3]);
        s += rn[0] * rn[0]; s += rn[1] * rn[1];
        s += rn[2] * rn[2]; s += rn[3] * rn[3];
        if (l < QL - 1) {
            __nv_bfloat16 h[4], lo[4];
            #pragma unroll
            for (int k = 0; k < 4; ++k) {
                h[k]  = __float2bfloat16(rn[k]);
                lo[k] = __float2bfloat16(rn[k] - __bfloat162float(h[k]));
            }
            *(__nv_bfloat162*)(hp + j)     = __nv_bfloat162(h[0], h[1]);
            *(__nv_bfloat162*)(hp + j + 2) = __nv_bfloat162(h[2], h[3]);
            *(__nv_bfloat162*)(lp + j)     = __nv_bfloat162(lo[0], lo[1]);
            *(__nv_bfloat162*)(lp + j + 2) = __nv_bfloat162(lo[2], lo[3]);
        }

        float4 qa;
        if (l == 0) {
            qa = q;
        } else {
            float4 o = *(const float4*)(qs + j);
            qa.x = o.x + q.x; qa.y = o.y + q.y;
            qa.z = o.z + q.z; qa.w = o.w + q.w;
        }
        *(float4*)(qs + j) = qa;

        if (l == QL - 1) {
            float4 xv = *(const float4*)(xp + j);
            float4 ov;
            ov.x = xv.x + (qa.x - xv.x);
            ov.y = xv.y + (qa.y - xv.y);
            ov.z = xv.z + (qa.z - xv.z);
            ov.w = xv.w + (qa.w - xv.w);
            *(float4*)(op + j) = ov;
        }
    }
    rsqp[tsub * 64 + tloc] = s;
    __syncthreads();
    if (tid < 64) {
        float r = ((rsqp[tid] + rsqp[64 + tid]) + rsqp[128 + tid]) + rsqp[192 + tid];
        g_rsq[tok0 + tid] = r;
        rsqs[tid] = r;
    }
    __syncthreads();
    if (tid == 0) {
        double cs = 0.0;
        for (int t = 0; t < 64; ++t) cs += (double)rsqs[t];
        atomicAdd(&g_commit[l], cs);
    }
}

// ---------------------------------------------------------------------------
__global__ void rvq_fin(float* __restrict__ out) {
    __shared__ double red[256];
    const int tid = threadIdx.x;
    double psum = 0.0;
    for (int l = 0; l < QL; ++l) {
        double s = 0.0;
        for (int k = tid; k < KC; k += 256) {
            double p = (double)g_cnt[l * KC + k] / (double)NTOK;
            s += p * log(p + 1e-10);
        }
        red[tid] = s;
        __syncthreads();
        for (int off = 128; off > 0; off >>= 1) {
            if (tid < off) red[tid] += red[tid + off];
            __syncthreads();
        }
        if (tid == 0) psum += exp(-red[0]);
        __syncthreads();
    }
    if (tid == 0) {
        double closs = 0.0;
        for (int l = 0; l < QL; ++l)
            closs += g_commit[l] / ((double)NTOK * (double)DD);
        out[SCLOFF]     = (float)(0.25 * closs);
        out[SCLOFF + 1] = (float)(psum / (double)QL);
    }
}

// ---------------------------------------------------------------------------
extern "C" void kernel_launch(void* const* d_in, const int* in_sizes, int n_in,
                              void* d_out, int out_size) {
    const float* x  = (const float*)d_in[0];
    const float* cb = (const float*)d_in[1];
    float* out = (float*)d_out;

    cudaFuncSetAttribute(rvq_gemm, cudaFuncAttributeMaxDynamicSharedMemorySize,
                         SMEM_GEMM);

    rvq_prep<<<(QL * KC + 255) / 256, 256>>>(cb);
    rvq_cbconv<<<(int)(((size_t)QL * KC * DD / 4 + 255) / 256), 256>>>(cb);
    rvq_init<<<NTOK / 64, 256>>>(x);
    for (int l = 0; l < QL; ++l) {
        rvq_gemm<<<NTOK / MTOK, 256, SMEM_GEMM>>>(l);
        rvq_update<<<NTOK / 64, 256>>>(l, x, cb, out);
    }
    rvq_fin<<<1, 256>>>(out);
}

// round 12
// speedup vs baseline: 1.7283x; 1.1143x over previous
#include <cuda_runtime.h>
#include <cuda_bf16.h>
#include <math.h>
#include <stdint.h>

// ---------------- problem constants ----------------
#define DD    512
#define KC    1024
#define QL    8
#define NTOK  16384
#define MTOK  128                  // tokens per GEMM CTA
#define NTL   128                  // codes per N-tile
#define KCH   32                   // dims per K-chunk
#define NITER 128                  // 8 ntiles * 16 chunks
#define NTHR  512                  // GEMM threads (16 warps)

#define IDXOFF ((size_t)NTOK * DD)
#define SCLOFF (IDXOFF + (size_t)NTOK * QL)

// ---------------- GEMM smem layout (bytes) ----------------
// per stage: Ahi[128 rows][80B], Alo, Bhi[128][80B], Blo  (64B data + 16B pad)
#define RSTRB  80u
#define OF_ALO 10240u
#define OF_BHI 20480u
#define OF_BLO 30720u
#define STG_SZ 40960u
#define NSTG   3
#define OF_CSQ 122880u
#define OF_RED (OF_CSQ + 4096u)    // cross-warp top2 merge: 128 x 16B
#define SMEM_GEMM (OF_RED + 2048)

// ---------------- device scratch (static; no cudaMalloc) ----------------
__device__ float          g_csq[QL * KC];
__device__ int            g_cnt[QL * KC];
__device__ double         g_commit[QL];
__device__ int            g_top1[NTOK];
__device__ int            g_top2[NTOK];
__device__ float          g_rsq[NTOK];
__device__ float          g_res [(size_t)NTOK * DD];
__device__ __nv_bfloat16  g_rhi [(size_t)NTOK * DD];
__device__ __nv_bfloat16  g_rlo [(size_t)NTOK * DD];
__device__ __nv_bfloat16  g_cbhi[(size_t)QL * KC * DD];
__device__ __nv_bfloat16  g_cblo[(size_t)QL * KC * DD];

// ---------------- helpers ----------------
__device__ __forceinline__ uint32_t smem_u32(const void* p) {
    uint32_t a;
    asm("{ .reg .u64 t; cvta.to.shared.u64 t, %1; cvt.u32.u64 %0, t; }"
        : "=r"(a) : "l"(p));
    return a;
}
__device__ __forceinline__ void cpa16(uint32_t dst, const void* src) {
    asm volatile("cp.async.cg.shared.global [%0], [%1], 16;" :: "r"(dst), "l"(src));
}
#define CP_COMMIT() asm volatile("cp.async.commit_group;" ::: "memory")
#define CP_WAIT2()  asm volatile("cp.async.wait_group 2;" ::: "memory")
#define CP_WAIT1()  asm volatile("cp.async.wait_group 1;" ::: "memory")
#define CP_WAIT0()  asm volatile("cp.async.wait_group 0;" ::: "memory")

#define LDSM4(r0, r1, r2, r3, a)                                               \
    asm volatile("ldmatrix.sync.aligned.m8n8.x4.shared.b16 {%0,%1,%2,%3}, [%4];" \
                 : "=r"(r0), "=r"(r1), "=r"(r2), "=r"(r3) : "r"(a))

#define MMA_BF16(c, a0, a1, a2, a3, b0, b1)                                    \
    asm volatile("mma.sync.aligned.m16n8k16.row.col.f32.bf16.bf16.f32 "        \
                 "{%0,%1,%2,%3}, {%4,%5,%6,%7}, {%8,%9}, {%0,%1,%2,%3};"       \
                 : "+f"((c)[0]), "+f"((c)[1]), "+f"((c)[2]), "+f"((c)[3])      \
                 : "r"(a0), "r"(a1), "r"(a2), "r"(a3), "r"(b0), "r"(b1))

// insert candidate (d,c) into top-2 (ascending c arrival)
#define TOP2_INS(v1, i1, v2, i2, d, c)                                         \
    do { if ((d) < (v1)) { v2 = v1; i2 = i1; v1 = (d); i1 = (c); }             \
         else if ((d) < (v2)) { v2 = (d); i2 = (c); } } while (0)

// merge (w1,j1,w2,j2) into (v1,i1,v2,i2); lex order (value, index)
__device__ __forceinline__ void top2_pairmerge(float& v1, int& i1,
                                               float& v2, int& i2,
                                               float w1, int j1,
                                               float w2, int j2) {
    if (w1 < v1 || (w1 == v1 && j1 < i1)) {
        if (v1 < w2 || (v1 == w2 && i1 < j2)) { v2 = v1; i2 = i1; }
        else                                  { v2 = w2; i2 = j2; }
        v1 = w1; i1 = j1;
    } else {
        if (w1 < v2 || (w1 == v2 && j1 < i2)) { v2 = w1; i2 = j1; }
    }
}
__device__ __forceinline__ void top2_merge(float& v1, int& i1,
                                           float& v2, int& i2, int off) {
    float w1 = __shfl_xor_sync(0xffffffffu, v1, off);
    int   j1 = __shfl_xor_sync(0xffffffffu, i1, off);
    float w2 = __shfl_xor_sync(0xffffffffu, v2, off);
    int   j2 = __shfl_xor_sync(0xffffffffu, i2, off);
    top2_pairmerge(v1, i1, v2, i2, w1, j1, w2, j2);
}

// ---------------------------------------------------------------------------
// prep: csq via coalesced 4-thread/row partials, zero stats
// ---------------------------------------------------------------------------
__global__ void rvq_prep(const float* __restrict__ cb) {
    __shared__ float pp[4 * 64];
    const int tid  = threadIdx.x;
    const int tsub = tid & 3, tloc = tid >> 2, dbase = tsub * 128;
    const int row  = blockIdx.x * 64 + tloc;
    const float* c = cb + (size_t)row * DD + dbase;
    float s = 0.f;
    #pragma unroll 4
    for (int j = 0; j < 128; j += 4) {
        float4 v = *(const float4*)(c + j);
        s += v.x * v.x; s += v.y * v.y; s += v.z * v.z; s += v.w * v.w;
    }
    pp[tsub * 64 + tloc] = s;
    __syncthreads();
    if (tid < 64)
        g_csq[blockIdx.x * 64 + tid] =
            ((pp[tid] + pp[64 + tid]) + pp[128 + tid]) + pp[192 + tid];
    int z = blockIdx.x * 64 + tid;   // 128 blocks x 256 covers 8192 with tid<64x4
    if (tid < 64) g_cnt[z] = 0;
    else if (tid >= 64 && tid < 128 && blockIdx.x == 0 && (tid - 64) < QL)
        g_commit[tid - 64] = 0.0;
}

// codebook fp32 -> bf16 hi/lo
__global__ void rvq_cbconv(const float* __restrict__ cb) {
    size_t i = ((size_t)blockIdx.x * blockDim.x + threadIdx.x) * 4;
    if (i >= (size_t)QL * KC * DD) return;
    float4 v = *(const float4*)(cb + i);
    float vv[4] = {v.x, v.y, v.z, v.w};
    __nv_bfloat16 h[4], lo[4];
    #pragma unroll
    for (int k = 0; k < 4; ++k) {
        h[k]  = __float2bfloat16(vv[k]);
        lo[k] = __float2bfloat16(vv[k] - __bfloat162float(h[k]));
    }
    *(__nv_bfloat162*)(g_cbhi + i)     = __nv_bfloat162(h[0], h[1]);
    *(__nv_bfloat162*)(g_cbhi + i + 2) = __nv_bfloat162(h[2], h[3]);
    *(__nv_bfloat162*)(g_cblo + i)     = __nv_bfloat162(lo[0], lo[1]);
    *(__nv_bfloat162*)(g_cblo + i + 2) = __nv_bfloat162(lo[2], lo[3]);
}

// init: x -> rhi/rlo (bf16) + rsq (exact partial scheme of the passing kernel)
__global__ void rvq_init(const float* __restrict__ x) {
    __shared__ float rsqp[4 * 64];
    const int tid  = threadIdx.x;
    const int tsub = tid & 3, tloc = tid >> 2, dbase = tsub * 128;
    const int tok  = blockIdx.x * 64 + tloc;
    const float* xp = x + (size_t)tok * DD + dbase;
    __nv_bfloat16* hp = g_rhi + (size_t)tok * DD + dbase;
    __nv_bfloat16* lp = g_rlo + (size_t)tok * DD + dbase;
    float s = 0.f;
    #pragma unroll 4
    for (int j = 0; j < 128; j += 4) {
        float4 v = *(const float4*)(xp + j);
        float vv[4] = {v.x, v.y, v.z, v.w};
        __nv_bfloat16 h[4], lo[4];
        #pragma unroll
        for (int k = 0; k < 4; ++k) {
            s += vv[k] * vv[k];
            h[k]  = __float2bfloat16(vv[k]);
            lo[k] = __float2bfloat16(vv[k] - __bfloat162float(h[k]));
        }
        *(__nv_bfloat162*)(hp + j)     = __nv_bfloat162(h[0], h[1]);
        *(__nv_bfloat162*)(hp + j + 2) = __nv_bfloat162(h[2], h[3]);
        *(__nv_bfloat162*)(lp + j)     = __nv_bfloat162(lo[0], lo[1]);
        *(__nv_bfloat162*)(lp + j + 2) = __nv_bfloat162(lo[2], lo[3]);
    }
    rsqp[tsub * 64 + tloc] = s;
    __syncthreads();
    if (tid < 64)
        g_rsq[blockIdx.x * 64 + tid] =
            ((rsqp[tid] + rsqp[64 + tid]) + rsqp[128 + tid]) + rsqp[192 + tid];
}

// ---------------------------------------------------------------------------
// GEMM: bf16 m16n8k16 3-term split; 16 warps (8 row-groups x 2 code-halves);
// epilogue nominates TOP-2 codes per token (exact rescore decides later).
// ---------------------------------------------------------------------------
__global__ void __launch_bounds__(NTHR, 1)
rvq_gemm(int l) {
    extern __shared__ char sm[];
    const uint32_t sb = smem_u32(sm);
    float* csq_sm = (float*)(sm + OF_CSQ);
    float* s_v1 = (float*)(sm + OF_RED);
    int*   s_i1 = (int*)(sm + OF_RED + 512);
    float* s_v2 = (float*)(sm + OF_RED + 1024);
    int*   s_i2 = (int*)(sm + OF_RED + 1536);

    const int tid  = threadIdx.x;
    const int wid  = tid >> 5;
    const int lane = tid & 31;
    const int wm   = wid & 7;        // row group
    const int wn   = wid >> 3;       // code half within ntile
    const int tok0 = blockIdx.x * MTOK;

    for (int i = tid; i < KC; i += NTHR) csq_sm[i] = g_csq[l * KC + i];

    const int row0 = wm * 16 + (lane >> 2);
    const int row1 = row0 + 8;
    const float rsq0 = g_rsq[tok0 + row0];
    const float rsq1 = g_rsq[tok0 + row1];

    const uint32_t lrow = lane & 15;
    const uint32_t acol = (uint32_t)((lane >> 4) << 4);
    const uint32_t aoff = (uint32_t)(wm * 16 + lrow) * RSTRB + acol;
    const uint32_t boff = lrow * RSTRB + acol + (uint32_t)(wn * 4) * (16u * RSTRB);

    const __nv_bfloat16* Ahi0 = g_rhi + (size_t)tok0 * DD;
    const __nv_bfloat16* Alo0 = g_rlo + (size_t)tok0 * DD;
    const __nv_bfloat16* Bhi0 = g_cbhi + (size_t)l * KC * DD;
    const __nv_bfloat16* Blo0 = g_cblo + (size_t)l * KC * DD;

    const float INF = __int_as_float(0x7f800000);
    float bv0 = INF, bv0b = INF, bv1 = INF, bv1b = INF;
    int   bi0 = 0,   bi0b = 0,   bi1 = 0,   bi1b = 0;

    float acc[8][4];

    // cp.async issue for iteration `it` (ntile = it>>4, chunk = it&15)
    auto issue = [&](int it) {
        const int ntb = (it >> 4) * NTL;
        const int d0  = (it & 15) * KCH;
        const uint32_t st = sb + (uint32_t)(it % NSTG) * STG_SZ;
        const int r = tid >> 2, g = tid & 3;       // 512 granules per array
        uint32_t doff = (uint32_t)r * RSTRB + (uint32_t)g * 16u;
        size_t   soff = (size_t)r * DD + d0 + g * 8;
        cpa16(st + doff,          Ahi0 + soff);
        cpa16(st + OF_ALO + doff, Alo0 + soff);
        size_t boffg = (size_t)(ntb + r) * DD + d0 + g * 8;
        cpa16(st + OF_BHI + doff, Bhi0 + boffg);
        cpa16(st + OF_BLO + doff, Blo0 + boffg);
    };

    issue(0); CP_COMMIT();
    issue(1); CP_COMMIT();

    #pragma unroll 1
    for (int it = 0; it < NITER; ++it) {
        if (it + 2 < NITER) { issue(it + 2); CP_COMMIT(); CP_WAIT2(); }
        else if (it + 1 < NITER) { CP_WAIT1(); }
        else { CP_WAIT0(); }
        __syncthreads();

        if ((it & 15) == 0) {
            #pragma unroll
            for (int t = 0; t < 8; ++t)
                #pragma unroll
                for (int k = 0; k < 4; ++k) acc[t][k] = 0.f;
        }

        const uint32_t stage = sb + (uint32_t)(it % NSTG) * STG_SZ;
        #pragma unroll
        for (int ks = 0; ks < 2; ++ks) {
            uint32_t ah0, ah1, ah2, ah3, al0, al1, al2, al3;
            LDSM4(ah0, ah1, ah2, ah3, stage + aoff + (uint32_t)ks * 32u);
            LDSM4(al0, al1, al2, al3, stage + OF_ALO + aoff + (uint32_t)ks * 32u);
            #pragma unroll
            for (int cg = 0; cg < 4; ++cg) {
                const uint32_t bo = boff + (uint32_t)cg * (16u * RSTRB)
                                         + (uint32_t)ks * 32u;
                uint32_t bh0, bh1, bh2, bh3, bl0, bl1, bl2, bl3;
                LDSM4(bh0, bh1, bh2, bh3, stage + OF_BHI + bo);
                LDSM4(bl0, bl1, bl2, bl3, stage + OF_BLO + bo);
                // n-group0 uses (m0, m2); group1 (m1, m3)
                MMA_BF16(acc[cg * 2],     ah0, ah1, ah2, ah3, bh0, bh2); // hi*hi
                MMA_BF16(acc[cg * 2 + 1], ah0, ah1, ah2, ah3, bh1, bh3);
                MMA_BF16(acc[cg * 2],     ah0, ah1, ah2, ah3, bl0, bl2); // hi*lo
                MMA_BF16(acc[cg * 2 + 1], ah0, ah1, ah2, ah3, bl1, bl3);
                MMA_BF16(acc[cg * 2],     al0, al1, al2, al3, bh0, bh2); // lo*hi
                MMA_BF16(acc[cg * 2 + 1], al0, al1, al2, al3, bh1, bh3);
            }
        }

        if ((it & 15) == 15) {
            const int ntb = (it >> 4) * NTL + wn * 64;
            #pragma unroll
            for (int nt = 0; nt < 8; ++nt) {
                int c0 = ntb + nt * 8 + 2 * (lane & 3);
                float q0 = csq_sm[c0], q1 = csq_sm[c0 + 1];
                float d00 = fmaf(-2.f, acc[nt][0], rsq0) + q0;
                float d01 = fmaf(-2.f, acc[nt][1], rsq0) + q1;
                float d10 = fmaf(-2.f, acc[nt][2], rsq1) + q0;
                float d11 = fmaf(-2.f, acc[nt][3], rsq1) + q1;
                TOP2_INS(bv0, bi0, bv0b, bi0b, d00, c0);
                TOP2_INS(bv0, bi0, bv0b, bi0b, d01, c0 + 1);
                TOP2_INS(bv1, bi1, bv1b, bi1b, d10, c0);
                TOP2_INS(bv1, bi1, bv1b, bi1b, d11, c0 + 1);
            }
        }
        __syncthreads();
    }

    // merge top-2 across the 4 lanes sharing each row
    top2_merge(bv0, bi0, bv0b, bi0b, 1);
    top2_merge(bv0, bi0, bv0b, bi0b, 2);
    top2_merge(bv1, bi1, bv1b, bi1b, 1);
    top2_merge(bv1, bi1, bv1b, bi1b, 2);

    // cross-warp merge between the two code-halves (wn==1 publishes)
    if (wn == 1 && (lane & 3) == 0) {
        s_v1[row0] = bv0; s_i1[row0] = bi0; s_v2[row0] = bv0b; s_i2[row0] = bi0b;
        s_v1[row1] = bv1; s_i1[row1] = bi1; s_v2[row1] = bv1b; s_i2[row1] = bi1b;
    }
    __syncthreads();
    if (wn == 0 && (lane & 3) == 0) {
        top2_pairmerge(bv0, bi0, bv0b, bi0b,
                       s_v1[row0], s_i1[row0], s_v2[row0], s_i2[row0]);
        top2_pairmerge(bv1, bi1, bv1b, bi1b,
                       s_v1[row1], s_i1[row1], s_v2[row1], s_i2[row1]);
        g_top1[tok0 + row0] = bi0;  g_top2[tok0 + row0] = bi0b;
        g_top1[tok0 + row1] = bi1;  g_top2[tok0 + row1] = bi1b;
    }
}

// ---------------------------------------------------------------------------
// update: EXACT fp32 rescore of the two nominated codes, then residual update
// (exact fp32 chain), next-level bf16 hi/lo, rsq, commit, counts, indices.
// Last level: quantized = x + ((x - res_new) - x)  (qsum RMW eliminated).
// ---------------------------------------------------------------------------
__global__ void __launch_bounds__(256)
rvq_update(int l, const float* __restrict__ x, const float* __restrict__ cb,
           float* __restrict__ out) {
    __shared__ float dotp[2][4][64];
    __shared__ int   widx[64];
    __shared__ float rsqp[4 * 64];
    __shared__ float rsqs[64];
    const int tid  = threadIdx.x;
    const int tsub = tid & 3, tloc = tid >> 2, dbase = tsub * 128;
    const int tok0 = blockIdx.x * 64;
    const int tok  = tok0 + tloc;

    const float* rp = (l == 0 ? x : g_res) + (size_t)tok * DD + dbase;

    // ---- rescore phase: exact fp32 dots for both candidates
    {
        const int cA = g_top1[tok];
        const int cB = g_top2[tok];
        const float* bA = cb + ((size_t)l * KC + cA) * DD + dbase;
        const float* bB = cb + ((size_t)l * KC + cB) * DD + dbase;
        float pA = 0.f, pB = 0.f;
        #pragma unroll 4
        for (int j = 0; j < 128; j += 4) {
            float4 r = *(const float4*)(rp + j);
            float4 a = *(const float4*)(bA + j);
            float4 b = *(const float4*)(bB + j);
            pA = fmaf(r.x, a.x, pA); pA = fmaf(r.y, a.y, pA);
            pA = fmaf(r.z, a.z, pA); pA = fmaf(r.w, a.w, pA);
            pB = fmaf(r.x, b.x, pB); pB = fmaf(r.y, b.y, pB);
            pB = fmaf(r.z, b.z, pB); pB = fmaf(r.w, b.w, pB);
        }
        dotp[0][tsub][tloc] = pA;
        dotp[1][tsub][tloc] = pB;
        __syncthreads();
        if (tsub == 0) {
            float dotA = ((dotp[0][0][tloc] + dotp[0][1][tloc])
                          + dotp[0][2][tloc]) + dotp[0][3][tloc];
            float dotB = ((dotp[1][0][tloc] + dotp[1][1][tloc])
                          + dotp[1][2][tloc]) + dotp[1][3][tloc];
            float rq = g_rsq[tok];
            float dA = fmaf(-2.f, dotA, rq) + g_csq[l * KC + cA];
            float dB = fmaf(-2.f, dotB, rq) + g_csq[l * KC + cB];
            int win = (dB < dA || (dB == dA && cB < cA)) ? cB : cA;
            widx[tloc] = win;
            out[IDXOFF + (size_t)tok * QL + l] = (float)win;
            atomicAdd(&g_cnt[l * KC + win], 1);
        }
        __syncthreads();
    }

    const int idx = widx[tloc];
    const float* qv = cb + ((size_t)l * KC + idx) * DD + dbase;
    float* rw = g_res + (size_t)tok * DD + dbase;
    const float* xp = x + (size_t)tok * DD + dbase;
    float* op = out + (size_t)tok * DD + dbase;
    __nv_bfloat16* hp = g_rhi + (size_t)tok * DD + dbase;
    __nv_bfloat16* lp = g_rlo + (size_t)tok * DD + dbase;

    float s = 0.f;
    #pragma unroll 4
    for (int j = 0; j < 128; j += 4) {
        float4 r = *(const float4*)(rp + j);
        float4 q = *(const float4*)(qv + j);
        float rn[4] = {r.x - q.x, r.y - q.y, r.z - q.z, r.w - q.w};
        s += rn[0] * rn[0]; s += rn[1] * rn[1];
        s += rn[2] * rn[2]; s += rn[3] * rn[3];
        if (l < QL - 1) {
            *(float4*)(rw + j) = make_float4(rn[0], rn[1], rn[2], rn[3]);
            __nv_bfloat16 h[4], lo[4];
            #pragma unroll
            for (int k = 0; k < 4; ++k) {
                h[k]  = __float2bfloat16(rn[k]);
                lo[k] = __float2bfloat16(rn[k] - __bfloat162float(h[k]));
            }
            *(__nv_bfloat162*)(hp + j)     = __nv_bfloat162(h[0], h[1]);
            *(__nv_bfloat162*)(hp + j + 2) = __nv_bfloat162(h[2], h[3]);
            *(__nv_bfloat162*)(lp + j)     = __nv_bfloat162(lo[0], lo[1]);
            *(__nv_bfloat162*)(lp + j + 2) = __nv_bfloat162(lo[2], lo[3]);
        } else {
            // quantized = x + (qsum - x), qsum = x - res_final
            float4 xv = *(const float4*)(xp + j);
            float qs0 = xv.x - rn[0], qs1 = xv.y - rn[1];
            float qs2 = xv.z - rn[2], qs3 = xv.w - rn[3];
            float4 ov;
            ov.x = xv.x + (qs0 - xv.x);
            ov.y = xv.y + (qs1 - xv.y);
            ov.z = xv.z + (qs2 - xv.z);
            ov.w = xv.w + (qs3 - xv.w);
            *(float4*)(op + j) = ov;
        }
    }
    rsqp[tsub * 64 + tloc] = s;
    __syncthreads();
    if (tid < 64) {
        float r = ((rsqp[tid] + rsqp[64 + tid]) + rsqp[128 + tid]) + rsqp[192 + tid];
        g_rsq[tok0 + tid] = r;
        rsqs[tid] = r;
    }
    __syncthreads();
    if (tid == 0) {
        double cs = 0.0;
        for (int t = 0; t < 64; ++t) cs += (double)rsqs[t];
        atomicAdd(&g_commit[l], cs);
    }
}

// ---------------------------------------------------------------------------
__global__ void rvq_fin(float* __restrict__ out) {
    __shared__ double red[256];
    const int tid = threadIdx.x;
    double psum = 0.0;
    for (int l = 0; l < QL; ++l) {
        double s = 0.0;
        for (int k = tid; k < KC; k += 256) {
            double p = (double)g_cnt[l * KC + k] / (double)NTOK;
            s += p * log(p + 1e-10);
        }
        red[tid] = s;
        __syncthreads();
        for (int off = 128; off > 0; off >>= 1) {
            if (tid < off) red[tid] += red[tid + off];
            __syncthreads();
        }
        if (tid == 0) psum += exp(-red[0]);
        __syncthreads();
    }
    if (tid == 0) {
        double closs = 0.0;
        for (int l = 0; l < QL; ++l)
            closs += g_commit[l] / ((double)NTOK * (double)DD);
        out[SCLOFF]     = (float)(0.25 * closs);
        out[SCLOFF + 1] = (float)(psum / (double)QL);
    }
}

// ---------------------------------------------------------------------------
extern "C" void kernel_launch(void* const* d_in, const int* in_sizes, int n_in,
                              void* d_out, int out_size) {
    const float* x  = (const float*)d_in[0];
    const float* cb = (const float*)d_in[1];
    float* out = (float*)d_out;

    cudaFuncSetAttribute(rvq_gemm, cudaFuncAttributeMaxDynamicSharedMemorySize,
                         SMEM_GEMM);

    rvq_prep<<<QL * KC / 64, 256>>>(cb);
    rvq_cbconv<<<(int)(((size_t)QL * KC * DD / 4 + 255) / 256), 256>>>(cb);
    rvq_init<<<NTOK / 64, 256>>>(x);
    for (int l = 0; l < QL; ++l) {
        rvq_gemm<<<NTOK / MTOK, NTHR, SMEM_GEMM>>>(l);
        rvq_update<<<NTOK / 64, 256>>>(l, x, cb, out);
    }
    rvq_fin<<<1, 256>>>(out);
}

// round 13
// speedup vs baseline: 1.9832x; 1.1475x over previous
#include <cuda_runtime.h>
#include <cuda_fp16.h>
#include <math.h>
#include <stdint.h>

// ---------------- problem constants ----------------
#define DD    512
#define KC    1024
#define QL    8
#define NTOK  16384
#define MTOK  128                  // tokens per GEMM CTA
#define NTL   128                  // codes per N-tile
#define KCH   32                   // dims per K-chunk
#define NITER 128                  // 8 ntiles * 16 chunks
#define NTHR  512                  // GEMM threads (16 warps)
#define NCAND 32                   // approx candidates kept per token
#define NRES  8                    // exact-rescored candidates per token

#define IDXOFF ((size_t)NTOK * DD)
#define SCLOFF (IDXOFF + (size_t)NTOK * QL)

// ---------------- GEMM smem layout (bytes) ----------------
// per stage: A[128 rows][80B], B[128 rows][80B]  (64B fp16 data + 16B pad)
#define RSTRB  80u
#define OF_B   10240u
#define STG_SZ 20480u
#define NSTG   3
#define OF_CSQ 61440u
#define SMEM_GEMM (61440 + 4096)

// ---------------- device scratch (static; no cudaMalloc) ----------------
__device__ float   g_csq[QL * KC];
__device__ int     g_cnt[QL * KC];
__device__ double  g_commit[QL];
__device__ float   g_cv[(size_t)NTOK * NCAND];   // approx candidate dists
__device__ int     g_ci[(size_t)NTOK * NCAND];   // candidate code ids
__device__ float   g_rsq[NTOK];
__device__ float   g_res [(size_t)NTOK * DD];
__device__ __half  g_rh  [(size_t)NTOK * DD];    // fp16 residual (nomination)
__device__ __half  g_cbh [(size_t)QL * KC * DD]; // fp16 codebook

// ---------------- helpers ----------------
__device__ __forceinline__ uint32_t smem_u32(const void* p) {
    uint32_t a;
    asm("{ .reg .u64 t; cvta.to.shared.u64 t, %1; cvt.u32.u64 %0, t; }"
        : "=r"(a) : "l"(p));
    return a;
}
__device__ __forceinline__ void cpa16(uint32_t dst, const void* src) {
    asm volatile("cp.async.cg.shared.global [%0], [%1], 16;" :: "r"(dst), "l"(src));
}
#define CP_COMMIT() asm volatile("cp.async.commit_group;" ::: "memory")
#define CP_WAIT2()  asm volatile("cp.async.wait_group 2;" ::: "memory")
#define CP_WAIT1()  asm volatile("cp.async.wait_group 1;" ::: "memory")
#define CP_WAIT0()  asm volatile("cp.async.wait_group 0;" ::: "memory")

#define LDSM4(r0, r1, r2, r3, a)                                               \
    asm volatile("ldmatrix.sync.aligned.m8n8.x4.shared.b16 {%0,%1,%2,%3}, [%4];" \
                 : "=r"(r0), "=r"(r1), "=r"(r2), "=r"(r3) : "r"(a))

#define MMA_FP16(c, a0, a1, a2, a3, b0, b1)                                    \
    asm volatile("mma.sync.aligned.m16n8k16.row.col.f32.f16.f16.f32 "          \
                 "{%0,%1,%2,%3}, {%4,%5,%6,%7}, {%8,%9}, {%0,%1,%2,%3};"       \
                 : "+f"((c)[0]), "+f"((c)[1]), "+f"((c)[2]), "+f"((c)[3])      \
                 : "r"(a0), "r"(a1), "r"(a2), "r"(a3), "r"(b0), "r"(b1))

// sorted top-4 insert (v0<=v1<=v2<=v3); strict < keeps earliest on equal
#define TOP4_INS(v0,i0,v1,i1,v2,i2,v3,i3,d,c) do {                             \
    if ((d) < (v3)) {                                                          \
        if ((d) < (v2)) { v3 = v2; i3 = i2;                                    \
            if ((d) < (v1)) { v2 = v1; i2 = i1;                                \
                if ((d) < (v0)) { v1 = v0; i1 = i0; v0 = (d); i0 = (c); }      \
                else            { v1 = (d); i1 = (c); } }                      \
            else { v2 = (d); i2 = (c); } }                                     \
        else { v3 = (d); i3 = (c); } }                                         \
} while (0)

// ---------------------------------------------------------------------------
// prep: csq via coalesced 4-thread/row partials, zero stats
// ---------------------------------------------------------------------------
__global__ void rvq_prep(const float* __restrict__ cb) {
    __shared__ float pp[4 * 64];
    const int tid  = threadIdx.x;
    const int tsub = tid & 3, tloc = tid >> 2, dbase = tsub * 128;
    const int row  = blockIdx.x * 64 + tloc;
    const float* c = cb + (size_t)row * DD + dbase;
    float s = 0.f;
    #pragma unroll 4
    for (int j = 0; j < 128; j += 4) {
        float4 v = *(const float4*)(c + j);
        s += v.x * v.x; s += v.y * v.y; s += v.z * v.z; s += v.w * v.w;
    }
    pp[tsub * 64 + tloc] = s;
    __syncthreads();
    if (tid < 64)
        g_csq[blockIdx.x * 64 + tid] =
            ((pp[tid] + pp[64 + tid]) + pp[128 + tid]) + pp[192 + tid];
    if (tid < 64) g_cnt[blockIdx.x * 64 + tid] = 0;
    else if (blockIdx.x == 0 && tid >= 64 && (tid - 64) < QL)
        g_commit[tid - 64] = 0.0;
}

// codebook fp32 -> fp16
__global__ void rvq_cbconv(const float* __restrict__ cb) {
    size_t i = ((size_t)blockIdx.x * blockDim.x + threadIdx.x) * 4;
    if (i >= (size_t)QL * KC * DD) return;
    float4 v = *(const float4*)(cb + i);
    __half2 h01 = __floats2half2_rn(v.x, v.y);
    __half2 h23 = __floats2half2_rn(v.z, v.w);
    *(__half2*)(g_cbh + i)     = h01;
    *(__half2*)(g_cbh + i + 2) = h23;
}

// init: x -> fp16 residual + rsq (exact partial scheme of the proven chain)
__global__ void rvq_init(const float* __restrict__ x) {
    __shared__ float rsqp[4 * 64];
    const int tid  = threadIdx.x;
    const int tsub = tid & 3, tloc = tid >> 2, dbase = tsub * 128;
    const int tok  = blockIdx.x * 64 + tloc;
    const float* xp = x + (size_t)tok * DD + dbase;
    __half* hp = g_rh + (size_t)tok * DD + dbase;
    float s = 0.f;
    #pragma unroll 4
    for (int j = 0; j < 128; j += 4) {
        float4 v = *(const float4*)(xp + j);
        s += v.x * v.x; s += v.y * v.y; s += v.z * v.z; s += v.w * v.w;
        *(__half2*)(hp + j)     = __floats2half2_rn(v.x, v.y);
        *(__half2*)(hp + j + 2) = __floats2half2_rn(v.z, v.w);
    }
    rsqp[tsub * 64 + tloc] = s;
    __syncthreads();
    if (tid < 64)
        g_rsq[blockIdx.x * 64 + tid] =
            ((rsqp[tid] + rsqp[64 + tid]) + rsqp[128 + tid]) + rsqp[192 + tid];
}

// ---------------------------------------------------------------------------
// GEMM (nomination): fp16 single-pass m16n8k16; per-lane TOP-4 candidates
// (8 lane-partitions x 4 = 32 candidates per token).
// ---------------------------------------------------------------------------
__global__ void __launch_bounds__(NTHR, 1)
rvq_gemm(int l) {
    extern __shared__ char sm[];
    const uint32_t sb = smem_u32(sm);
    float* csq_sm = (float*)(sm + OF_CSQ);

    const int tid  = threadIdx.x;
    const int wid  = tid >> 5;
    const int lane = tid & 31;
    const int wm   = wid & 7;        // row group
    const int wn   = wid >> 3;       // code half within ntile
    const int tok0 = blockIdx.x * MTOK;

    for (int i = tid; i < KC; i += NTHR) csq_sm[i] = g_csq[l * KC + i];

    const int row0 = wm * 16 + (lane >> 2);
    const int row1 = row0 + 8;
    const float rsq0 = g_rsq[tok0 + row0];
    const float rsq1 = g_rsq[tok0 + row1];

    const uint32_t lrow = lane & 15;
    const uint32_t acol = (uint32_t)((lane >> 4) << 4);
    const uint32_t aoff = (uint32_t)(wm * 16 + lrow) * RSTRB + acol;
    const uint32_t boff = lrow * RSTRB + acol + (uint32_t)(wn * 4) * (16u * RSTRB);

    const __half* Ah0 = g_rh + (size_t)tok0 * DD;
    const __half* Bh0 = g_cbh + (size_t)l * KC * DD;

    const float INF = __int_as_float(0x7f800000);
    float a_v0 = INF, a_v1 = INF, a_v2 = INF, a_v3 = INF;   // row0 top-4
    int   a_i0 = 0,   a_i1 = 0,   a_i2 = 0,   a_i3 = 0;
    float b_v0 = INF, b_v1 = INF, b_v2 = INF, b_v3 = INF;   // row1 top-4
    int   b_i0 = 0,   b_i1 = 0,   b_i2 = 0,   b_i3 = 0;

    float acc[8][4];

    auto issue = [&](int it) {
        const int ntb = (it >> 4) * NTL;
        const int d0  = (it & 15) * KCH;
        const uint32_t st = sb + (uint32_t)(it % NSTG) * STG_SZ;
        const int r = tid >> 2, g = tid & 3;      // 512 granules of 16B per array
        uint32_t doff = (uint32_t)r * RSTRB + (uint32_t)g * 16u;
        cpa16(st + doff,        Ah0 + (size_t)r * DD + d0 + g * 8);
        cpa16(st + OF_B + doff, Bh0 + (size_t)(ntb + r) * DD + d0 + g * 8);
    };

    issue(0); CP_COMMIT();
    issue(1); CP_COMMIT();

    #pragma unroll 1
    for (int it = 0; it < NITER; ++it) {
        if (it + 2 < NITER) { issue(it + 2); CP_COMMIT(); CP_WAIT2(); }
        else if (it + 1 < NITER) { CP_WAIT1(); }
        else { CP_WAIT0(); }
        __syncthreads();

        if ((it & 15) == 0) {
            #pragma unroll
            for (int t = 0; t < 8; ++t)
                #pragma unroll
                for (int k = 0; k < 4; ++k) acc[t][k] = 0.f;
        }

        const uint32_t stage = sb + (uint32_t)(it % NSTG) * STG_SZ;
        #pragma unroll
        for (int ks = 0; ks < 2; ++ks) {
            uint32_t a0, a1, a2, a3;
            LDSM4(a0, a1, a2, a3, stage + aoff + (uint32_t)ks * 32u);
            #pragma unroll
            for (int cg = 0; cg < 4; ++cg) {
                const uint32_t bo = boff + (uint32_t)cg * (16u * RSTRB)
                                         + (uint32_t)ks * 32u;
                uint32_t b0, b1, b2, b3;
                LDSM4(b0, b1, b2, b3, stage + OF_B + bo);
                // n-group0 uses (m0, m2); group1 (m1, m3)
                MMA_FP16(acc[cg * 2],     a0, a1, a2, a3, b0, b2);
                MMA_FP16(acc[cg * 2 + 1], a0, a1, a2, a3, b1, b3);
            }
        }

        if ((it & 15) == 15) {
            const int ntb = (it >> 4) * NTL + wn * 64;
            #pragma unroll
            for (int nt = 0; nt < 8; ++nt) {
                int c0 = ntb + nt * 8 + 2 * (lane & 3);
                float q0 = csq_sm[c0], q1 = csq_sm[c0 + 1];
                float d00 = fmaf(-2.f, acc[nt][0], rsq0) + q0;
                float d01 = fmaf(-2.f, acc[nt][1], rsq0) + q1;
                float d10 = fmaf(-2.f, acc[nt][2], rsq1) + q0;
                float d11 = fmaf(-2.f, acc[nt][3], rsq1) + q1;
                TOP4_INS(a_v0,a_i0,a_v1,a_i1,a_v2,a_i2,a_v3,a_i3, d00, c0);
                TOP4_INS(a_v0,a_i0,a_v1,a_i1,a_v2,a_i2,a_v3,a_i3, d01, c0 + 1);
                TOP4_INS(b_v0,b_i0,b_v1,b_i1,b_v2,b_i2,b_v3,b_i3, d10, c0);
                TOP4_INS(b_v0,b_i0,b_v1,b_i1,b_v2,b_i2,b_v3,b_i3, d11, c0 + 1);
            }
        }
        __syncthreads();
    }

    // each lane owns a disjoint code partition; write its top-4 per row
    const int s0 = (wn * 4 + (lane & 3)) * 4;
    {
        size_t base = (size_t)(tok0 + row0) * NCAND + s0;
        g_cv[base]     = a_v0; g_ci[base]     = a_i0;
        g_cv[base + 1] = a_v1; g_ci[base + 1] = a_i1;
        g_cv[base + 2] = a_v2; g_ci[base + 2] = a_i2;
        g_cv[base + 3] = a_v3; g_ci[base + 3] = a_i3;
        base = (size_t)(tok0 + row1) * NCAND + s0;
        g_cv[base]     = b_v0; g_ci[base]     = b_i0;
        g_cv[base + 1] = b_v1; g_ci[base + 1] = b_i1;
        g_cv[base + 2] = b_v2; g_ci[base + 2] = b_i2;
        g_cv[base + 3] = b_v3; g_ci[base + 3] = b_i3;
    }
}

// ---------------------------------------------------------------------------
// update: select approx-top-8 of 32 candidates, EXACT fp32 rescore (proven
// chain) decides argmin; then residual update, next-level fp16, rsq, commit.
// Last level: quantized = x + ((x - res_new) - x).
// ---------------------------------------------------------------------------
__global__ void __launch_bounds__(256)
rvq_update(int l, const float* __restrict__ x, const float* __restrict__ cb,
           float* __restrict__ out) {
    __shared__ float cvs[64][NCAND];
    __shared__ int   cis[64][NCAND];
    __shared__ int   sel[64][NRES];
    __shared__ float dotp[NRES][4][64];
    __shared__ int   widx[64];
    __shared__ float rsqp[4 * 64];
    __shared__ float rsqs[64];
    const int tid  = threadIdx.x;
    const int tsub = tid & 3, tloc = tid >> 2, dbase = tsub * 128;
    const int tok0 = blockIdx.x * 64;
    const int tok  = tok0 + tloc;

    // load 32 candidates
    #pragma unroll
    for (int k = 0; k < 8; ++k) {
        int j = tsub * 8 + k;
        cvs[tloc][j] = g_cv[(size_t)tok * NCAND + j];
        cis[tloc][j] = g_ci[(size_t)tok * NCAND + j];
    }
    __syncthreads();

    // approx-select top-NRES (lex (val, idx); deterministic)
    if (tsub == 0) {
        #pragma unroll 1
        for (int s = 0; s < NRES; ++s) {
            float bv = cvs[tloc][0]; int bi = cis[tloc][0]; int bp = 0;
            #pragma unroll 1
            for (int j = 1; j < NCAND; ++j) {
                float v = cvs[tloc][j]; int ii = cis[tloc][j];
                if (v < bv || (v == bv && ii < bi)) { bv = v; bi = ii; bp = j; }
            }
            sel[tloc][s] = bi;
            cvs[tloc][bp] = __int_as_float(0x7f800000);
        }
    }
    __syncthreads();

    const float* rp = (l == 0 ? x : g_res) + (size_t)tok * DD + dbase;

    // exact fp32 rescore of NRES candidates (sequential fmaf, proven chain)
    {
        const float* bp[NRES];
        float p[NRES];
        #pragma unroll
        for (int c = 0; c < NRES; ++c) {
            bp[c] = cb + ((size_t)l * KC + sel[tloc][c]) * DD + dbase;
            p[c] = 0.f;
        }
        #pragma unroll 2
        for (int j = 0; j < 128; j += 4) {
            float4 r = *(const float4*)(rp + j);
            #pragma unroll
            for (int c = 0; c < NRES; ++c) {
                float4 b = *(const float4*)(bp[c] + j);
                p[c] = fmaf(r.x, b.x, p[c]); p[c] = fmaf(r.y, b.y, p[c]);
                p[c] = fmaf(r.z, b.z, p[c]); p[c] = fmaf(r.w, b.w, p[c]);
            }
        }
        #pragma unroll
        for (int c = 0; c < NRES; ++c) dotp[c][tsub][tloc] = p[c];
    }
    __syncthreads();
    if (tsub == 0) {
        float rq = g_rsq[tok];
        float bd = __int_as_float(0x7f800000); int bi = 0x7fffffff;
        #pragma unroll
        for (int c = 0; c < NRES; ++c) {
            int code = sel[tloc][c];
            float dot = ((dotp[c][0][tloc] + dotp[c][1][tloc])
                         + dotp[c][2][tloc]) + dotp[c][3][tloc];
            float d = fmaf(-2.f, dot, rq) + g_csq[l * KC + code];
            if (d < bd || (d == bd && code < bi)) { bd = d; bi = code; }
        }
        widx[tloc] = bi;
        out[IDXOFF + (size_t)tok * QL + l] = (float)bi;
        atomicAdd(&g_cnt[l * KC + bi], 1);
    }
    __syncthreads();

    const int idx = widx[tloc];
    const float* qv = cb + ((size_t)l * KC + idx) * DD + dbase;
    float* rw = g_res + (size_t)tok * DD + dbase;
    const float* xp = x + (size_t)tok * DD + dbase;
    float* op = out + (size_t)tok * DD + dbase;
    __half* hp = g_rh + (size_t)tok * DD + dbase;

    float s = 0.f;
    #pragma unroll 4
    for (int j = 0; j < 128; j += 4) {
        float4 r = *(const float4*)(rp + j);
        float4 q = *(const float4*)(qv + j);
        float rn[4] = {r.x - q.x, r.y - q.y, r.z - q.z, r.w - q.w};
        s += rn[0] * rn[0]; s += rn[1] * rn[1];
        s += rn[2] * rn[2]; s += rn[3] * rn[3];
        if (l < QL - 1) {
            *(float4*)(rw + j) = make_float4(rn[0], rn[1], rn[2], rn[3]);
            *(__half2*)(hp + j)     = __floats2half2_rn(rn[0], rn[1]);
            *(__half2*)(hp + j + 2) = __floats2half2_rn(rn[2], rn[3]);
        } else {
            float4 xv = *(const float4*)(xp + j);
            float qs0 = xv.x - rn[0], qs1 = xv.y - rn[1];
            float qs2 = xv.z - rn[2], qs3 = xv.w - rn[3];
            float4 ov;
            ov.x = xv.x + (qs0 - xv.x);
            ov.y = xv.y + (qs1 - xv.y);
            ov.z = xv.z + (qs2 - xv.z);
            ov.w = xv.w + (qs3 - xv.w);
            *(float4*)(op + j) = ov;
        }
    }
    rsqp[tsub * 64 + tloc] = s;
    __syncthreads();
    if (tid < 64) {
        float r = ((rsqp[tid] + rsqp[64 + tid]) + rsqp[128 + tid]) + rsqp[192 + tid];
        g_rsq[tok0 + tid] = r;
        rsqs[tid] = r;
    }
    __syncthreads();
    if (tid == 0) {
        double cs = 0.0;
        for (int t = 0; t < 64; ++t) cs += (double)rsqs[t];
        atomicAdd(&g_commit[l], cs);
    }
}

// ---------------------------------------------------------------------------
__global__ void rvq_fin(float* __restrict__ out) {
    __shared__ double red[256];
    const int tid = threadIdx.x;
    double psum = 0.0;
    for (int l = 0; l < QL; ++l) {
        double s = 0.0;
        for (int k = tid; k < KC; k += 256) {
            double p = (double)g_cnt[l * KC + k] / (double)NTOK;
            s += p * log(p + 1e-10);
        }
        red[tid] = s;
        __syncthreads();
        for (int off = 128; off > 0; off >>= 1) {
            if (tid < off) red[tid] += red[tid + off];
            __syncthreads();
        }
        if (tid == 0) psum += exp(-red[0]);
        __syncthreads();
    }
    if (tid == 0) {
        double closs = 0.0;
        for (int l = 0; l < QL; ++l)
            closs += g_commit[l] / ((double)NTOK * (double)DD);
        out[SCLOFF]     = (float)(0.25 * closs);
        out[SCLOFF + 1] = (float)(psum / (double)QL);
    }
}

// ---------------------------------------------------------------------------
extern "C" void kernel_launch(void* const* d_in, const int* in_sizes, int n_in,
                              void* d_out, int out_size) {
    const float* x  = (const float*)d_in[0];
    const float* cb = (const float*)d_in[1];
    float* out = (float*)d_out;

    cudaFuncSetAttribute(rvq_gemm, cudaFuncAttributeMaxDynamicSharedMemorySize,
                         SMEM_GEMM);

    rvq_prep<<<QL * KC / 64, 256>>>(cb);
    rvq_cbconv<<<(int)(((size_t)QL * KC * DD / 4 + 255) / 256), 256>>>(cb);
    rvq_init<<<NTOK / 64, 256>>>(x);
    for (int l = 0; l < QL; ++l) {
        rvq_gemm<<<NTOK / MTOK, NTHR, SMEM_GEMM>>>(l);
        rvq_update<<<NTOK / 64, 256>>>(l, x, cb, out);
    }
    rvq_fin<<<1, 256>>>(out);
}

// round 14
// speedup vs baseline: 2.0142x; 1.0156x over previous
#include <cuda_runtime.h>
#include <cuda_fp16.h>
#include <math.h>
#include <stdint.h>

// ---------------- problem constants ----------------
#define DD    512
#define KC    1024
#define QL    8
#define NTOK  16384
#define MTOK  128                  // tokens per CTA
#define NTL   128                  // codes per N-tile
#define KCH   32                   // dims per K-chunk
#define NITER 128                  // 8 ntiles * 16 chunks
#define NTHR  512                  // 16 warps
#define NCAND 32                   // approx candidates kept per token
#define NRES  8                    // exact-rescored candidates per token

#define IDXOFF ((size_t)NTOK * DD)
#define SCLOFF (IDXOFF + (size_t)NTOK * QL)

// ---------------- smem layout (bytes) ----------------
// nomination stages: A[128][80B] + B[128][80B] per stage, 3 stages
#define RSTRB  80u
#define OF_B   10240u
#define STG_SZ 20480u
#define NSTG   3
#define OF_CSQ 61440u              // 4KB csq (never aliased)
// phase-2 scratch aliases the stage region [0, 61440)
#define OF_CV   0u                 // 128*32*4  = 16384
#define OF_CI   16384u             // 16384
#define OF_SEL  32768u             // 128*8*4   = 4096
#define OF_DOTP 36864u             // 8*4*128*4 = 16384
#define OF_WIDX 53248u             // 512
#define OF_RSQP 53760u             // 4*128*4   = 2048
#define OF_RSQS 55808u             // 512
#define SMEM_LVL (61440 + 4096)

// ---------------- device scratch (static; no cudaMalloc) ----------------
__device__ float   g_csq[QL * KC];
__device__ int     g_cnt[QL * KC];
__device__ double  g_commit[QL];
__device__ float   g_rsq[NTOK];
__device__ float   g_res [(size_t)NTOK * DD];
__device__ __half  g_rh  [(size_t)NTOK * DD];    // fp16 residual (nomination)
__device__ __half  g_cbh [(size_t)QL * KC * DD]; // fp16 codebook

// ---------------- helpers ----------------
__device__ __forceinline__ uint32_t smem_u32(const void* p) {
    uint32_t a;
    asm("{ .reg .u64 t; cvta.to.shared.u64 t, %1; cvt.u32.u64 %0, t; }"
        : "=r"(a) : "l"(p));
    return a;
}
__device__ __forceinline__ void cpa16(uint32_t dst, const void* src) {
    asm volatile("cp.async.cg.shared.global [%0], [%1], 16;" :: "r"(dst), "l"(src));
}
#define CP_COMMIT() asm volatile("cp.async.commit_group;" ::: "memory")
#define CP_WAIT2()  asm volatile("cp.async.wait_group 2;" ::: "memory")
#define CP_WAIT1()  asm volatile("cp.async.wait_group 1;" ::: "memory")
#define CP_WAIT0()  asm volatile("cp.async.wait_group 0;" ::: "memory")

#define LDSM4(r0, r1, r2, r3, a)                                               \
    asm volatile("ldmatrix.sync.aligned.m8n8.x4.shared.b16 {%0,%1,%2,%3}, [%4];" \
                 : "=r"(r0), "=r"(r1), "=r"(r2), "=r"(r3) : "r"(a))

#define MMA_FP16(c, a0, a1, a2, a3, b0, b1)                                    \
    asm volatile("mma.sync.aligned.m16n8k16.row.col.f32.f16.f16.f32 "          \
                 "{%0,%1,%2,%3}, {%4,%5,%6,%7}, {%8,%9}, {%0,%1,%2,%3};"       \
                 : "+f"((c)[0]), "+f"((c)[1]), "+f"((c)[2]), "+f"((c)[3])      \
                 : "r"(a0), "r"(a1), "r"(a2), "r"(a3), "r"(b0), "r"(b1))

// sorted top-4 insert (v0<=v1<=v2<=v3); strict < keeps earliest on equal
#define TOP4_INS(v0,i0,v1,i1,v2,i2,v3,i3,d,c) do {                             \
    if ((d) < (v3)) {                                                          \
        if ((d) < (v2)) { v3 = v2; i3 = i2;                                    \
            if ((d) < (v1)) { v2 = v1; i2 = i1;                                \
                if ((d) < (v0)) { v1 = v0; i1 = i0; v0 = (d); i0 = (c); }      \
                else            { v1 = (d); i1 = (c); } }                      \
            else { v2 = (d); i2 = (c); } }                                     \
        else { v3 = (d); i3 = (c); } }                                         \
} while (0)

// ---------------------------------------------------------------------------
// prep: csq via coalesced 4-thread/row partials, zero stats
// ---------------------------------------------------------------------------
__global__ void rvq_prep(const float* __restrict__ cb) {
    __shared__ float pp[4 * 64];
    const int tid  = threadIdx.x;
    const int tsub = tid & 3, tloc = tid >> 2, dbase = tsub * 128;
    const int row  = blockIdx.x * 64 + tloc;
    const float* c = cb + (size_t)row * DD + dbase;
    float s = 0.f;
    #pragma unroll 4
    for (int j = 0; j < 128; j += 4) {
        float4 v = *(const float4*)(c + j);
        s += v.x * v.x; s += v.y * v.y; s += v.z * v.z; s += v.w * v.w;
    }
    pp[tsub * 64 + tloc] = s;
    __syncthreads();
    if (tid < 64)
        g_csq[blockIdx.x * 64 + tid] =
            ((pp[tid] + pp[64 + tid]) + pp[128 + tid]) + pp[192 + tid];
    if (tid < 64) g_cnt[blockIdx.x * 64 + tid] = 0;
    else if (blockIdx.x == 0 && tid >= 64 && (tid - 64) < QL)
        g_commit[tid - 64] = 0.0;
}

// codebook fp32 -> fp16
__global__ void rvq_cbconv(const float* __restrict__ cb) {
    size_t i = ((size_t)blockIdx.x * blockDim.x + threadIdx.x) * 4;
    if (i >= (size_t)QL * KC * DD) return;
    float4 v = *(const float4*)(cb + i);
    *(__half2*)(g_cbh + i)     = __floats2half2_rn(v.x, v.y);
    *(__half2*)(g_cbh + i + 2) = __floats2half2_rn(v.z, v.w);
}

// init: x -> fp16 residual + rsq (exact partial scheme of the proven chain)
__global__ void rvq_init(const float* __restrict__ x) {
    __shared__ float rsqp[4 * 64];
    const int tid  = threadIdx.x;
    const int tsub = tid & 3, tloc = tid >> 2, dbase = tsub * 128;
    const int tok  = blockIdx.x * 64 + tloc;
    const float* xp = x + (size_t)tok * DD + dbase;
    __half* hp = g_rh + (size_t)tok * DD + dbase;
    float s = 0.f;
    #pragma unroll 4
    for (int j = 0; j < 128; j += 4) {
        float4 v = *(const float4*)(xp + j);
        s += v.x * v.x; s += v.y * v.y; s += v.z * v.z; s += v.w * v.w;
        *(__half2*)(hp + j)     = __floats2half2_rn(v.x, v.y);
        *(__half2*)(hp + j + 2) = __floats2half2_rn(v.z, v.w);
    }
    rsqp[tsub * 64 + tloc] = s;
    __syncthreads();
    if (tid < 64)
        g_rsq[blockIdx.x * 64 + tid] =
            ((rsqp[tid] + rsqp[64 + tid]) + rsqp[128 + tid]) + rsqp[192 + tid];
}

// ---------------------------------------------------------------------------
// fused per-level kernel: fp16 nomination GEMM (top-4 per lane-partition)
// -> smem candidates -> approx top-8 -> EXACT fp32 rescore (proven chain)
// -> residual/output update. One wave: 128 CTAs x 512 threads.
// ---------------------------------------------------------------------------
__global__ void __launch_bounds__(NTHR, 1)
rvq_level(int l, const float* __restrict__ x, const float* __restrict__ cb,
          float* __restrict__ out) {
    extern __shared__ char sm[];
    const uint32_t sb = smem_u32(sm);
    float* csq_sm = (float*)(sm + OF_CSQ);

    const int tid  = threadIdx.x;
    const int wid  = tid >> 5;
    const int lane = tid & 31;
    const int wm   = wid & 7;        // row group
    const int wn   = wid >> 3;       // code half within ntile
    const int tok0 = blockIdx.x * MTOK;

    for (int i = tid; i < KC; i += NTHR) csq_sm[i] = g_csq[l * KC + i];

    const int row0 = wm * 16 + (lane >> 2);
    const int row1 = row0 + 8;
    const float rsq0 = g_rsq[tok0 + row0];
    const float rsq1 = g_rsq[tok0 + row1];

    const uint32_t lrow = lane & 15;
    const uint32_t acol = (uint32_t)((lane >> 4) << 4);
    const uint32_t aoff = (uint32_t)(wm * 16 + lrow) * RSTRB + acol;
    const uint32_t boff = lrow * RSTRB + acol + (uint32_t)(wn * 4) * (16u * RSTRB);

    const __half* Ah0 = g_rh + (size_t)tok0 * DD;
    const __half* Bh0 = g_cbh + (size_t)l * KC * DD;

    const float INF = __int_as_float(0x7f800000);
    float a_v0 = INF, a_v1 = INF, a_v2 = INF, a_v3 = INF;   // row0 top-4
    int   a_i0 = 0,   a_i1 = 0,   a_i2 = 0,   a_i3 = 0;
    float b_v0 = INF, b_v1 = INF, b_v2 = INF, b_v3 = INF;   // row1 top-4
    int   b_i0 = 0,   b_i1 = 0,   b_i2 = 0,   b_i3 = 0;

    float acc[8][4];

    auto issue = [&](int it) {
        const int ntb = (it >> 4) * NTL;
        const int d0  = (it & 15) * KCH;
        const uint32_t st = sb + (uint32_t)(it % NSTG) * STG_SZ;
        const int r = tid >> 2, g = tid & 3;      // 512 granules of 16B per array
        uint32_t doff = (uint32_t)r * RSTRB + (uint32_t)g * 16u;
        cpa16(st + doff,        Ah0 + (size_t)r * DD + d0 + g * 8);
        cpa16(st + OF_B + doff, Bh0 + (size_t)(ntb + r) * DD + d0 + g * 8);
    };

    issue(0); CP_COMMIT();
    issue(1); CP_COMMIT();

    #pragma unroll 1
    for (int it = 0; it < NITER; ++it) {
        if (it + 2 < NITER) { issue(it + 2); CP_COMMIT(); CP_WAIT2(); }
        else if (it + 1 < NITER) { CP_WAIT1(); }
        else { CP_WAIT0(); }
        __syncthreads();

        if ((it & 15) == 0) {
            #pragma unroll
            for (int t = 0; t < 8; ++t)
                #pragma unroll
                for (int k = 0; k < 4; ++k) acc[t][k] = 0.f;
        }

        const uint32_t stage = sb + (uint32_t)(it % NSTG) * STG_SZ;
        #pragma unroll
        for (int ks = 0; ks < 2; ++ks) {
            uint32_t a0, a1, a2, a3;
            LDSM4(a0, a1, a2, a3, stage + aoff + (uint32_t)ks * 32u);
            #pragma unroll
            for (int cg = 0; cg < 4; ++cg) {
                const uint32_t bo = boff + (uint32_t)cg * (16u * RSTRB)
                                         + (uint32_t)ks * 32u;
                uint32_t b0, b1, b2, b3;
                LDSM4(b0, b1, b2, b3, stage + OF_B + bo);
                // n-group0 uses (m0, m2); group1 (m1, m3)
                MMA_FP16(acc[cg * 2],     a0, a1, a2, a3, b0, b2);
                MMA_FP16(acc[cg * 2 + 1], a0, a1, a2, a3, b1, b3);
            }
        }

        if ((it & 15) == 15) {
            const int ntb = (it >> 4) * NTL + wn * 64;
            #pragma unroll
            for (int nt = 0; nt < 8; ++nt) {
                int c0 = ntb + nt * 8 + 2 * (lane & 3);
                float q0 = csq_sm[c0], q1 = csq_sm[c0 + 1];
                float d00 = fmaf(-2.f, acc[nt][0], rsq0) + q0;
                float d01 = fmaf(-2.f, acc[nt][1], rsq0) + q1;
                float d10 = fmaf(-2.f, acc[nt][2], rsq1) + q0;
                float d11 = fmaf(-2.f, acc[nt][3], rsq1) + q1;
                TOP4_INS(a_v0,a_i0,a_v1,a_i1,a_v2,a_i2,a_v3,a_i3, d00, c0);
                TOP4_INS(a_v0,a_i0,a_v1,a_i1,a_v2,a_i2,a_v3,a_i3, d01, c0 + 1);
                TOP4_INS(b_v0,b_i0,b_v1,b_i1,b_v2,b_i2,b_v3,b_i3, d10, c0);
                TOP4_INS(b_v0,b_i0,b_v1,b_i1,b_v2,b_i2,b_v3,b_i3, d11, c0 + 1);
            }
        }
        __syncthreads();
    }

    // ---- publish candidates to smem (stage region is dead now)
    float* CV = (float*)(sm + OF_CV);
    int*   CI = (int*)(sm + OF_CI);
    {
        const int s0 = (wn * 4 + (lane & 3)) * 4;
        int b0 = row0 * NCAND + s0;
        CV[b0]     = a_v0; CI[b0]     = a_i0;
        CV[b0 + 1] = a_v1; CI[b0 + 1] = a_i1;
        CV[b0 + 2] = a_v2; CI[b0 + 2] = a_i2;
        CV[b0 + 3] = a_v3; CI[b0 + 3] = a_i3;
        int b1 = row1 * NCAND + s0;
        CV[b1]     = b_v0; CI[b1]     = b_i0;
        CV[b1 + 1] = b_v1; CI[b1 + 1] = b_i1;
        CV[b1 + 2] = b_v2; CI[b1 + 2] = b_i2;
        CV[b1 + 3] = b_v3; CI[b1 + 3] = b_i3;
    }
    __syncthreads();

    // ---- phase 2: 4 threads per token, 128 tokens
    int*   SEL  = (int*)(sm + OF_SEL);
    float* DOTP = (float*)(sm + OF_DOTP);    // [NRES][4][128]
    int*   WIDX = (int*)(sm + OF_WIDX);
    float* RSQP = (float*)(sm + OF_RSQP);
    float* RSQS = (float*)(sm + OF_RSQS);

    const int tsub = tid & 3, tloc = tid >> 2;    // tloc 0..127
    const int tok  = tok0 + tloc;
    const int dbase = tsub * 128;

    // approx-select top-NRES (lex (val, idx); same scan order as before)
    if (tsub == 0) {
        #pragma unroll 1
        for (int s = 0; s < NRES; ++s) {
            float bv = CV[tloc * NCAND]; int bi = CI[tloc * NCAND]; int bp = 0;
            #pragma unroll 1
            for (int j = 1; j < NCAND; ++j) {
                float v = CV[tloc * NCAND + j]; int ii = CI[tloc * NCAND + j];
                if (v < bv || (v == bv && ii < bi)) { bv = v; bi = ii; bp = j; }
            }
            SEL[tloc * NRES + s] = bi;
            CV[tloc * NCAND + bp] = INF;
        }
    }
    __syncthreads();

    const float* rp = (l == 0 ? x : g_res) + (size_t)tok * DD + dbase;

    // exact fp32 rescore of NRES candidates (sequential fmaf, proven chain)
    {
        const float* bp[NRES];
        float p[NRES];
        #pragma unroll
        for (int c = 0; c < NRES; ++c) {
            bp[c] = cb + ((size_t)l * KC + SEL[tloc * NRES + c]) * DD + dbase;
            p[c] = 0.f;
        }
        #pragma unroll 2
        for (int j = 0; j < 128; j += 4) {
            float4 r = *(const float4*)(rp + j);
            #pragma unroll
            for (int c = 0; c < NRES; ++c) {
                float4 b = *(const float4*)(bp[c] + j);
                p[c] = fmaf(r.x, b.x, p[c]); p[c] = fmaf(r.y, b.y, p[c]);
                p[c] = fmaf(r.z, b.z, p[c]); p[c] = fmaf(r.w, b.w, p[c]);
            }
        }
        #pragma unroll
        for (int c = 0; c < NRES; ++c)
            DOTP[c * 512 + tsub * 128 + tloc] = p[c];
    }
    __syncthreads();
    if (tsub == 0) {
        float rq = g_rsq[tok];
        float bd = INF; int bi = 0x7fffffff;
        #pragma unroll
        for (int c = 0; c < NRES; ++c) {
            int code = SEL[tloc * NRES + c];
            float dot = ((DOTP[c * 512 + tloc] + DOTP[c * 512 + 128 + tloc])
                         + DOTP[c * 512 + 256 + tloc]) + DOTP[c * 512 + 384 + tloc];
            float d = fmaf(-2.f, dot, rq) + csq_sm[code];
            if (d < bd || (d == bd && code < bi)) { bd = d; bi = code; }
        }
        WIDX[tloc] = bi;
        out[IDXOFF + (size_t)tok * QL + l] = (float)bi;
        atomicAdd(&g_cnt[l * KC + bi], 1);
    }
    __syncthreads();

    const int idx = WIDX[tloc];
    const float* qv = cb + ((size_t)l * KC + idx) * DD + dbase;
    float* rw = g_res + (size_t)tok * DD + dbase;
    const float* xp = x + (size_t)tok * DD + dbase;
    float* op = out + (size_t)tok * DD + dbase;
    __half* hp = g_rh + (size_t)tok * DD + dbase;

    float s = 0.f;
    #pragma unroll 4
    for (int j = 0; j < 128; j += 4) {
        float4 r = *(const float4*)(rp + j);
        float4 q = *(const float4*)(qv + j);
        float rn[4] = {r.x - q.x, r.y - q.y, r.z - q.z, r.w - q.w};
        s += rn[0] * rn[0]; s += rn[1] * rn[1];
        s += rn[2] * rn[2]; s += rn[3] * rn[3];
        if (l < QL - 1) {
            *(float4*)(rw + j) = make_float4(rn[0], rn[1], rn[2], rn[3]);
            *(__half2*)(hp + j)     = __floats2half2_rn(rn[0], rn[1]);
            *(__half2*)(hp + j + 2) = __floats2half2_rn(rn[2], rn[3]);
        } else {
            float4 xv = *(const float4*)(xp + j);
            float qs0 = xv.x - rn[0], qs1 = xv.y - rn[1];
            float qs2 = xv.z - rn[2], qs3 = xv.w - rn[3];
            float4 ov;
            ov.x = xv.x + (qs0 - xv.x);
            ov.y = xv.y + (qs1 - xv.y);
            ov.z = xv.z + (qs2 - xv.z);
            ov.w = xv.w + (qs3 - xv.w);
            *(float4*)(op + j) = ov;
        }
    }
    RSQP[tsub * 128 + tloc] = s;
    __syncthreads();
    if (tid < 128) {
        float r = ((RSQP[tid] + RSQP[128 + tid]) + RSQP[256 + tid])
                  + RSQP[384 + tid];
        g_rsq[tok0 + tid] = r;
        RSQS[tid] = r;
    }
    __syncthreads();
    if (tid == 0) {
        double cs = 0.0;
        for (int t = 0; t < MTOK; ++t) cs += (double)RSQS[t];
        atomicAdd(&g_commit[l], cs);
    }
}

// ---------------------------------------------------------------------------
__global__ void rvq_fin(float* __restrict__ out) {
    __shared__ double red[256];
    const int tid = threadIdx.x;
    double psum = 0.0;
    for (int l = 0; l < QL; ++l) {
        double s = 0.0;
        for (int k = tid; k < KC; k += 256) {
            double p = (double)g_cnt[l * KC + k] / (double)NTOK;
            s += p * log(p + 1e-10);
        }
        red[tid] = s;
        __syncthreads();
        for (int off = 128; off > 0; off >>= 1) {
            if (tid < off) red[tid] += red[tid + off];
            __syncthreads();
        }
        if (tid == 0) psum += exp(-red[0]);
        __syncthreads();
    }
    if (tid == 0) {
        double closs = 0.0;
        for (int l = 0; l < QL; ++l)
            closs += g_commit[l] / ((double)NTOK * (double)DD);
        out[SCLOFF]     = (float)(0.25 * closs);
        out[SCLOFF + 1] = (float)(psum / (double)QL);
    }
}

// ---------------------------------------------------------------------------
extern "C" void kernel_launch(void* const* d_in, const int* in_sizes, int n_in,
                              void* d_out, int out_size) {
    const float* x  = (const float*)d_in[0];
    const float* cb = (const float*)d_in[1];
    float* out = (float*)d_out;

    cudaFuncSetAttribute(rvq_level, cudaFuncAttributeMaxDynamicSharedMemorySize,
                         SMEM_LVL);

    rvq_prep<<<QL * KC / 64, 256>>>(cb);
    rvq_cbconv<<<(int)(((size_t)QL * KC * DD / 4 + 255) / 256), 256>>>(cb);
    rvq_init<<<NTOK / 64, 256>>>(x);
    for (int l = 0; l < QL; ++l)
        rvq_level<<<NTOK / MTOK, NTHR, SMEM_LVL>>>(l, x, cb, out);
    rvq_fin<<<1, 256>>>(out);
}

// round 15
// speedup vs baseline: 2.1073x; 1.0462x over previous
#include <cuda_runtime.h>
#include <cuda_fp16.h>
#include <math.h>
#include <stdint.h>

// ---------------- problem constants ----------------
#define DD    512
#define KC    1024
#define QL    8
#define NTOK  16384
#define MTOK  64                   // tokens per CTA
#define NTL   128                  // codes per N-tile
#define KCH   32                   // dims per K-chunk
#define NITER 128                  // 8 ntiles * 16 chunks
#define NTHR  256                  // 8 warps
#define NCAND 32                   // approx candidates kept per token
#define NRES  8                    // exact-rescored candidates per token

#define IDXOFF ((size_t)NTOK * DD)
#define SCLOFF (IDXOFF + (size_t)NTOK * QL)

// ---------------- smem layout (bytes) ----------------
// per stage: A[64 rows][80B] (5120) + B[128 rows][80B] (10240)
#define RSTRB  80u
#define OF_B   5120u
#define STG_SZ 15360u
#define NSTG   3
#define OF_CSQ 46080u              // 4KB csq (never aliased)
// phase-2 scratch aliases the stage region [0, 46080)
#define OF_CV   0u                 // 64*32*4 = 8192
#define OF_CI   8192u              // 8192
#define OF_SEL  16384u             // 64*8*4 = 2048
#define OF_DOTP 18432u             // 8*4*64*4 = 8192
#define OF_WIDX 26624u             // 256
#define OF_RSQP 26880u             // 1024
#define OF_RSQS 27904u             // 256
#define SMEM_LVL (46080 + 4096)

// ---------------- device scratch (static; no cudaMalloc) ----------------
__device__ float   g_csq[QL * KC];
__device__ int     g_cnt[QL * KC];
__device__ double  g_commit[QL];
__device__ float   g_rsq[NTOK];
__device__ float   g_res [(size_t)NTOK * DD];
__device__ __half  g_rh  [(size_t)NTOK * DD];    // fp16 residual (nomination)
__device__ __half  g_cbh [(size_t)QL * KC * DD]; // fp16 codebook

// ---------------- helpers ----------------
__device__ __forceinline__ uint32_t smem_u32(const void* p) {
    uint32_t a;
    asm("{ .reg .u64 t; cvta.to.shared.u64 t, %1; cvt.u32.u64 %0, t; }"
        : "=r"(a) : "l"(p));
    return a;
}
__device__ __forceinline__ void cpa16(uint32_t dst, const void* src) {
    asm volatile("cp.async.cg.shared.global [%0], [%1], 16;" :: "r"(dst), "l"(src));
}
#define CP_COMMIT() asm volatile("cp.async.commit_group;" ::: "memory")
#define CP_WAIT2()  asm volatile("cp.async.wait_group 2;" ::: "memory")
#define CP_WAIT1()  asm volatile("cp.async.wait_group 1;" ::: "memory")
#define CP_WAIT0()  asm volatile("cp.async.wait_group 0;" ::: "memory")

#define LDSM4(r0, r1, r2, r3, a)                                               \
    asm volatile("ldmatrix.sync.aligned.m8n8.x4.shared.b16 {%0,%1,%2,%3}, [%4];" \
                 : "=r"(r0), "=r"(r1), "=r"(r2), "=r"(r3) : "r"(a))

#define MMA_FP16(c, a0, a1, a2, a3, b0, b1)                                    \
    asm volatile("mma.sync.aligned.m16n8k16.row.col.f32.f16.f16.f32 "          \
                 "{%0,%1,%2,%3}, {%4,%5,%6,%7}, {%8,%9}, {%0,%1,%2,%3};"       \
                 : "+f"((c)[0]), "+f"((c)[1]), "+f"((c)[2]), "+f"((c)[3])      \
                 : "r"(a0), "r"(a1), "r"(a2), "r"(a3), "r"(b0), "r"(b1))

// sorted top-4 insert (v0<=v1<=v2<=v3); strict < keeps earliest on equal
#define TOP4_INS(v0,i0,v1,i1,v2,i2,v3,i3,d,c) do {                             \
    if ((d) < (v3)) {                                                          \
        if ((d) < (v2)) { v3 = v2; i3 = i2;                                    \
            if ((d) < (v1)) { v2 = v1; i2 = i1;                                \
                if ((d) < (v0)) { v1 = v0; i1 = i0; v0 = (d); i0 = (c); }      \
                else            { v1 = (d); i1 = (c); } }                      \
            else { v2 = (d); i2 = (c); } }                                     \
        else { v3 = (d); i3 = (c); } }                                         \
} while (0)

// ---------------------------------------------------------------------------
// prep: csq via coalesced 4-thread/row partials, zero stats
// ---------------------------------------------------------------------------
__global__ void rvq_prep(const float* __restrict__ cb) {
    __shared__ float pp[4 * 64];
    const int tid  = threadIdx.x;
    const int tsub = tid & 3, tloc = tid >> 2, dbase = tsub * 128;
    const int row  = blockIdx.x * 64 + tloc;
    const float* c = cb + (size_t)row * DD + dbase;
    float s = 0.f;
    #pragma unroll 4
    for (int j = 0; j < 128; j += 4) {
        float4 v = *(const float4*)(c + j);
        s += v.x * v.x; s += v.y * v.y; s += v.z * v.z; s += v.w * v.w;
    }
    pp[tsub * 64 + tloc] = s;
    __syncthreads();
    if (tid < 64)
        g_csq[blockIdx.x * 64 + tid] =
            ((pp[tid] + pp[64 + tid]) + pp[128 + tid]) + pp[192 + tid];
    if (tid < 64) g_cnt[blockIdx.x * 64 + tid] = 0;
    else if (blockIdx.x == 0 && tid >= 64 && (tid - 64) < QL)
        g_commit[tid - 64] = 0.0;
}

// codebook fp32 -> fp16
__global__ void rvq_cbconv(const float* __restrict__ cb) {
    size_t i = ((size_t)blockIdx.x * blockDim.x + threadIdx.x) * 4;
    if (i >= (size_t)QL * KC * DD) return;
    float4 v = *(const float4*)(cb + i);
    *(__half2*)(g_cbh + i)     = __floats2half2_rn(v.x, v.y);
    *(__half2*)(g_cbh + i + 2) = __floats2half2_rn(v.z, v.w);
}

// init: x -> fp16 residual + rsq (exact partial scheme of the proven chain)
__global__ void rvq_init(const float* __restrict__ x) {
    __shared__ float rsqp[4 * 64];
    const int tid  = threadIdx.x;
    const int tsub = tid & 3, tloc = tid >> 2, dbase = tsub * 128;
    const int tok  = blockIdx.x * 64 + tloc;
    const float* xp = x + (size_t)tok * DD + dbase;
    __half* hp = g_rh + (size_t)tok * DD + dbase;
    float s = 0.f;
    #pragma unroll 4
    for (int j = 0; j < 128; j += 4) {
        float4 v = *(const float4*)(xp + j);
        s += v.x * v.x; s += v.y * v.y; s += v.z * v.z; s += v.w * v.w;
        *(__half2*)(hp + j)     = __floats2half2_rn(v.x, v.y);
        *(__half2*)(hp + j + 2) = __floats2half2_rn(v.z, v.w);
    }
    rsqp[tsub * 64 + tloc] = s;
    __syncthreads();
    if (tid < 64)
        g_rsq[blockIdx.x * 64 + tid] =
            ((rsqp[tid] + rsqp[64 + tid]) + rsqp[128 + tid]) + rsqp[192 + tid];
}

// ---------------------------------------------------------------------------
// fused per-level kernel, 64 tokens per CTA, 2 CTAs/SM co-residency:
// fp16 nomination GEMM (top-4 per lane-partition) -> smem candidates
// -> approx top-8 -> EXACT fp32 rescore (proven chain) -> residual update.
// ---------------------------------------------------------------------------
__global__ void __launch_bounds__(NTHR, 2)
rvq_level(int l, const float* __restrict__ x, const float* __restrict__ cb,
          float* __restrict__ out) {
    extern __shared__ char sm[];
    const uint32_t sb = smem_u32(sm);
    float* csq_sm = (float*)(sm + OF_CSQ);

    const int tid  = threadIdx.x;
    const int wid  = tid >> 5;
    const int lane = tid & 31;
    const int wm   = wid & 3;        // row group (4 x 16 rows = 64)
    const int wn   = wid >> 2;       // code half within ntile
    const int tok0 = blockIdx.x * MTOK;

    for (int i = tid; i < KC; i += NTHR) csq_sm[i] = g_csq[l * KC + i];

    const int row0 = wm * 16 + (lane >> 2);
    const int row1 = row0 + 8;
    const float rsq0 = g_rsq[tok0 + row0];
    const float rsq1 = g_rsq[tok0 + row1];

    const uint32_t lrow = lane & 15;
    const uint32_t acol = (uint32_t)((lane >> 4) << 4);
    const uint32_t aoff = (uint32_t)(wm * 16 + lrow) * RSTRB + acol;
    const uint32_t boff = lrow * RSTRB + acol + (uint32_t)(wn * 4) * (16u * RSTRB);

    const __half* Ah0 = g_rh + (size_t)tok0 * DD;
    const __half* Bh0 = g_cbh + (size_t)l * KC * DD;

    const float INF = __int_as_float(0x7f800000);
    float a_v0 = INF, a_v1 = INF, a_v2 = INF, a_v3 = INF;   // row0 top-4
    int   a_i0 = 0,   a_i1 = 0,   a_i2 = 0,   a_i3 = 0;
    float b_v0 = INF, b_v1 = INF, b_v2 = INF, b_v3 = INF;   // row1 top-4
    int   b_i0 = 0,   b_i1 = 0,   b_i2 = 0,   b_i3 = 0;

    float acc[8][4];

    auto issue = [&](int it) {
        const int ntb = (it >> 4) * NTL;
        const int d0  = (it & 15) * KCH;
        const uint32_t st = sb + (uint32_t)(it % NSTG) * STG_SZ;
        // A: 64 rows x 4 granules = 256 (1/thread); B: 128 rows x 4 = 512 (2/thread)
        {
            const int r = tid >> 2, g = tid & 3;
            cpa16(st + (uint32_t)r * RSTRB + (uint32_t)g * 16u,
                  Ah0 + (size_t)r * DD + d0 + g * 8);
        }
        #pragma unroll
        for (int i = 0; i < 2; ++i) {
            const int gi = i * 256 + tid;
            const int r = gi >> 2, g = gi & 3;
            cpa16(st + OF_B + (uint32_t)r * RSTRB + (uint32_t)g * 16u,
                  Bh0 + (size_t)(ntb + r) * DD + d0 + g * 8);
        }
    };

    issue(0); CP_COMMIT();
    issue(1); CP_COMMIT();

    #pragma unroll 1
    for (int it = 0; it < NITER; ++it) {
        if (it + 2 < NITER) { issue(it + 2); CP_COMMIT(); CP_WAIT2(); }
        else if (it + 1 < NITER) { CP_WAIT1(); }
        else { CP_WAIT0(); }
        __syncthreads();

        if ((it & 15) == 0) {
            #pragma unroll
            for (int t = 0; t < 8; ++t)
                #pragma unroll
                for (int k = 0; k < 4; ++k) acc[t][k] = 0.f;
        }

        const uint32_t stage = sb + (uint32_t)(it % NSTG) * STG_SZ;
        #pragma unroll
        for (int ks = 0; ks < 2; ++ks) {
            uint32_t a0, a1, a2, a3;
            LDSM4(a0, a1, a2, a3, stage + aoff + (uint32_t)ks * 32u);
            #pragma unroll
            for (int cg = 0; cg < 4; ++cg) {
                const uint32_t bo = boff + (uint32_t)cg * (16u * RSTRB)
                                         + (uint32_t)ks * 32u;
                uint32_t b0, b1, b2, b3;
                LDSM4(b0, b1, b2, b3, stage + OF_B + bo);
                // n-group0 uses (m0, m2); group1 (m1, m3)
                MMA_FP16(acc[cg * 2],     a0, a1, a2, a3, b0, b2);
                MMA_FP16(acc[cg * 2 + 1], a0, a1, a2, a3, b1, b3);
            }
        }

        if ((it & 15) == 15) {
            const int ntb = (it >> 4) * NTL + wn * 64;
            #pragma unroll
            for (int nt = 0; nt < 8; ++nt) {
                int c0 = ntb + nt * 8 + 2 * (lane & 3);
                float q0 = csq_sm[c0], q1 = csq_sm[c0 + 1];
                float d00 = fmaf(-2.f, acc[nt][0], rsq0) + q0;
                float d01 = fmaf(-2.f, acc[nt][1], rsq0) + q1;
                float d10 = fmaf(-2.f, acc[nt][2], rsq1) + q0;
                float d11 = fmaf(-2.f, acc[nt][3], rsq1) + q1;
                TOP4_INS(a_v0,a_i0,a_v1,a_i1,a_v2,a_i2,a_v3,a_i3, d00, c0);
                TOP4_INS(a_v0,a_i0,a_v1,a_i1,a_v2,a_i2,a_v3,a_i3, d01, c0 + 1);
                TOP4_INS(b_v0,b_i0,b_v1,b_i1,b_v2,b_i2,b_v3,b_i3, d10, c0);
                TOP4_INS(b_v0,b_i0,b_v1,b_i1,b_v2,b_i2,b_v3,b_i3, d11, c0 + 1);
            }
        }
        __syncthreads();
    }

    // ---- publish candidates to smem (stage region is dead now)
    float* CV = (float*)(sm + OF_CV);
    int*   CI = (int*)(sm + OF_CI);
    {
        const int s0 = (wn * 4 + (lane & 3)) * 4;
        int b0 = row0 * NCAND + s0;
        CV[b0]     = a_v0; CI[b0]     = a_i0;
        CV[b0 + 1] = a_v1; CI[b0 + 1] = a_i1;
        CV[b0 + 2] = a_v2; CI[b0 + 2] = a_i2;
        CV[b0 + 3] = a_v3; CI[b0 + 3] = a_i3;
        int b1 = row1 * NCAND + s0;
        CV[b1]     = b_v0; CI[b1]     = b_i0;
        CV[b1 + 1] = b_v1; CI[b1 + 1] = b_i1;
        CV[b1 + 2] = b_v2; CI[b1 + 2] = b_i2;
        CV[b1 + 3] = b_v3; CI[b1 + 3] = b_i3;
    }
    __syncthreads();

    // ---- phase 2: 4 threads per token, 64 tokens
    int*   SEL  = (int*)(sm + OF_SEL);
    float* DOTP = (float*)(sm + OF_DOTP);    // [NRES][4][64]
    int*   WIDX = (int*)(sm + OF_WIDX);
    float* RSQP = (float*)(sm + OF_RSQP);
    float* RSQS = (float*)(sm + OF_RSQS);

    const int tsub = tid & 3, tloc = tid >> 2;    // tloc 0..63
    const int tok  = tok0 + tloc;
    const int dbase = tsub * 128;

    // approx-select top-NRES (lex (val, idx); same scan order as before)
    if (tsub == 0) {
        #pragma unroll 1
        for (int s = 0; s < NRES; ++s) {
            float bv = CV[tloc * NCAND]; int bi = CI[tloc * NCAND]; int bp = 0;
            #pragma unroll 1
            for (int j = 1; j < NCAND; ++j) {
                float v = CV[tloc * NCAND + j]; int ii = CI[tloc * NCAND + j];
                if (v < bv || (v == bv && ii < bi)) { bv = v; bi = ii; bp = j; }
            }
            SEL[tloc * NRES + s] = bi;
            CV[tloc * NCAND + bp] = INF;
        }
    }
    __syncthreads();

    const float* rp = (l == 0 ? x : g_res) + (size_t)tok * DD + dbase;

    // exact fp32 rescore of NRES candidates (sequential fmaf, proven chain)
    {
        const float* bp[NRES];
        float p[NRES];
        #pragma unroll
        for (int c = 0; c < NRES; ++c) {
            bp[c] = cb + ((size_t)l * KC + SEL[tloc * NRES + c]) * DD + dbase;
            p[c] = 0.f;
        }
        #pragma unroll 2
        for (int j = 0; j < 128; j += 4) {
            float4 r = *(const float4*)(rp + j);
            #pragma unroll
            for (int c = 0; c < NRES; ++c) {
                float4 b = *(const float4*)(bp[c] + j);
                p[c] = fmaf(r.x, b.x, p[c]); p[c] = fmaf(r.y, b.y, p[c]);
                p[c] = fmaf(r.z, b.z, p[c]); p[c] = fmaf(r.w, b.w, p[c]);
            }
        }
        #pragma unroll
        for (int c = 0; c < NRES; ++c)
            DOTP[c * 256 + tsub * 64 + tloc] = p[c];
    }
    __syncthreads();
    if (tsub == 0) {
        float rq = g_rsq[tok];
        float bd = INF; int bi = 0x7fffffff;
        #pragma unroll
        for (int c = 0; c < NRES; ++c) {
            int code = SEL[tloc * NRES + c];
            float dot = ((DOTP[c * 256 + tloc] + DOTP[c * 256 + 64 + tloc])
                         + DOTP[c * 256 + 128 + tloc]) + DOTP[c * 256 + 192 + tloc];
            float d = fmaf(-2.f, dot, rq) + csq_sm[code];
            if (d < bd || (d == bd && code < bi)) { bd = d; bi = code; }
        }
        WIDX[tloc] = bi;
        out[IDXOFF + (size_t)tok * QL + l] = (float)bi;
        atomicAdd(&g_cnt[l * KC + bi], 1);
    }
    __syncthreads();

    const int idx = WIDX[tloc];
    const float* qv = cb + ((size_t)l * KC + idx) * DD + dbase;
    float* rw = g_res + (size_t)tok * DD + dbase;
    const float* xp = x + (size_t)tok * DD + dbase;
    float* op = out + (size_t)tok * DD + dbase;
    __half* hp = g_rh + (size_t)tok * DD + dbase;

    float s = 0.f;
    #pragma unroll 4
    for (int j = 0; j < 128; j += 4) {
        float4 r = *(const float4*)(rp + j);
        float4 q = *(const float4*)(qv + j);
        float rn[4] = {r.x - q.x, r.y - q.y, r.z - q.z, r.w - q.w};
        s += rn[0] * rn[0]; s += rn[1] * rn[1];
        s += rn[2] * rn[2]; s += rn[3] * rn[3];
        if (l < QL - 1) {
            *(float4*)(rw + j) = make_float4(rn[0], rn[1], rn[2], rn[3]);
            *(__half2*)(hp + j)     = __floats2half2_rn(rn[0], rn[1]);
            *(__half2*)(hp + j + 2) = __floats2half2_rn(rn[2], rn[3]);
        } else {
            float4 xv = *(const float4*)(xp + j);
            float qs0 = xv.x - rn[0], qs1 = xv.y - rn[1];
            float qs2 = xv.z - rn[2], qs3 = xv.w - rn[3];
            float4 ov;
            ov.x = xv.x + (qs0 - xv.x);
            ov.y = xv.y + (qs1 - xv.y);
            ov.z = xv.z + (qs2 - xv.z);
            ov.w = xv.w + (qs3 - xv.w);
            *(float4*)(op + j) = ov;
        }
    }
    RSQP[tsub * 64 + tloc] = s;
    __syncthreads();
    if (tid < 64) {
        float r = ((RSQP[tid] + RSQP[64 + tid]) + RSQP[128 + tid])
                  + RSQP[192 + tid];
        g_rsq[tok0 + tid] = r;
        RSQS[tid] = r;
    }
    __syncthreads();
    if (tid == 0) {
        double cs = 0.0;
        for (int t = 0; t < MTOK; ++t) cs += (double)RSQS[t];
        atomicAdd(&g_commit[l], cs);
    }
}

// ---------------------------------------------------------------------------
__global__ void rvq_fin(float* __restrict__ out) {
    __shared__ double red[256];
    const int tid = threadIdx.x;
    double psum = 0.0;
    for (int l = 0; l < QL; ++l) {
        double s = 0.0;
        for (int k = tid; k < KC; k += 256) {
            double p = (double)g_cnt[l * KC + k] / (double)NTOK;
            s += p * log(p + 1e-10);
        }
        red[tid] = s;
        __syncthreads();
        for (int off = 128; off > 0; off >>= 1) {
            if (tid < off) red[tid] += red[tid + off];
            __syncthreads();
        }
        if (tid == 0) psum += exp(-red[0]);
        __syncthreads();
    }
    if (tid == 0) {
        double closs = 0.0;
        for (int l = 0; l < QL; ++l)
            closs += g_commit[l] / ((double)NTOK * (double)DD);
        out[SCLOFF]     = (float)(0.25 * closs);
        out[SCLOFF + 1] = (float)(psum / (double)QL);
    }
}

// ---------------------------------------------------------------------------
extern "C" void kernel_launch(void* const* d_in, const int* in_sizes, int n_in,
                              void* d_out, int out_size) {
    const float* x  = (const float*)d_in[0];
    const float* cb = (const float*)d_in[1];
    float* out = (float*)d_out;

    cudaFuncSetAttribute(rvq_level, cudaFuncAttributeMaxDynamicSharedMemorySize,
                         SMEM_LVL);

    rvq_prep<<<QL * KC / 64, 256>>>(cb);
    rvq_cbconv<<<(int)(((size_t)QL * KC * DD / 4 + 255) / 256), 256>>>(cb);
    rvq_init<<<NTOK / 64, 256>>>(x);
    for (int l = 0; l < QL; ++l)
        rvq_level<<<NTOK / MTOK, NTHR, SMEM_LVL>>>(l, x, cb, out);
    rvq_fin<<<1, 256>>>(out);
}